// round 2
// baseline (speedup 1.0000x reference)
#include <cuda_runtime.h>
#include <cuda_bf16.h>
#include <math.h>
#include <stdint.h>

#define HID   4096
#define BOT   64
#define RDIM  48
#define NSLOT 1024
#define TOPK  8
#define VB    256
#define HU    1024
#define TMAX  4096

typedef __nv_bfloat16 bf16;

// ---------------- static scratch ----------------
__device__ bf16  g_Hb[(size_t)TMAX * HID];        // 32 MB
__device__ bf16  g_Wu1b[HU * HID];                // 8 MB
__device__ bf16  g_Wqb[BOT * HID];
__device__ bf16  g_Avalb[NSLOT * HID];            // 8 MB
__device__ bf16  g_Wvdb[VB * HID];
__device__ bf16  g_Wvub[HID * VB];
__device__ float g_Y[(size_t)TMAX * HU];          // 16 MB
__device__ float g_Qpart[4][TMAX * BOT];          // 4 MB
__device__ float g_Q[TMAX * BOT];
__device__ bf16  g_Qb[TMAX * BOT];
__device__ float g_rk[NSLOT * RDIM];
__device__ bf16  g_Mslotb[NSLOT * BOT];
__device__ float g_scores[(size_t)TMAX * NSLOT];  // 16 MB
__device__ float g_ADpart[8][NSLOT * VB];         // 8 MB
__device__ float g_auxdown[NSLOT * VB];
__device__ bf16  g_downb[TMAX * VB];
__device__ float g_logvar[TMAX];
__device__ float g_gate[TMAX];
__device__ float g_mean[1];

__device__ __forceinline__ float gelu_tanh(float x) {
    float x3 = x * x * x;
    return 0.5f * x * (1.0f + tanhf(0.7978845608028654f * (x + 0.044715f * x3)));
}
__device__ __forceinline__ float sigmoidf(float x) { return 1.0f / (1.0f + expf(-x)); }

// ---------------- ldmatrix / mma helpers ----------------
__device__ __forceinline__ void ldsm_x4(uint32_t& r0, uint32_t& r1, uint32_t& r2, uint32_t& r3,
                                        const bf16* p) {
    uint32_t addr = (uint32_t)__cvta_generic_to_shared(p);
    asm volatile("ldmatrix.sync.aligned.m8n8.x4.shared.b16 {%0,%1,%2,%3}, [%4];"
                 : "=r"(r0), "=r"(r1), "=r"(r2), "=r"(r3) : "r"(addr));
}
__device__ __forceinline__ void mma_bf16(float* c, const uint32_t* a, const uint32_t* b) {
    asm volatile(
        "mma.sync.aligned.m16n8k16.row.col.f32.bf16.bf16.f32 "
        "{%0,%1,%2,%3}, {%4,%5,%6,%7}, {%8,%9}, {%0,%1,%2,%3};"
        : "+f"(c[0]), "+f"(c[1]), "+f"(c[2]), "+f"(c[3])
        : "r"(a[0]), "r"(a[1]), "r"(a[2]), "r"(a[3]), "r"(b[0]), "r"(b[1]));
}

// ---------------- tensor-core GEMM: C[M,N] = A[M,K] @ B[N,K]^T ----------------
// BM=128 fixed, BK=32, 256 threads, warps 4(m) x 2(n). Warp tile 32 x (BN/2).
// gridDim.z = deterministic split-K; z-partials written to C + z*M*N.
// EPI: 0 = plain fp32 store; 1 = out = hs + gate[row]*acc.
template<int BN, int EPI>
__global__ void mma_nt(const bf16* __restrict__ A, const bf16* __restrict__ B,
                       float* __restrict__ C, int M, int N, int K,
                       const float* __restrict__ hs, const float* __restrict__ gate) {
    constexpr int BM = 128, BK = 32, LDS = BK + 8;   // 40 halves per row
    constexpr int WN = BN / 2, NT = WN / 8, NP = NT / 2;
    __shared__ bf16 As[BM * LDS];
    __shared__ bf16 Bs[BN * LDS];

    const int tid = threadIdx.x, lane = tid & 31, w = tid >> 5;
    const int wm = w & 3, wn = w >> 2;
    const int m0 = blockIdx.y * BM, n0 = blockIdx.x * BN;
    const int kpart = K / gridDim.z;
    const int kbeg = blockIdx.z * kpart;
    float* Cout = C + (size_t)blockIdx.z * M * N;

    const int lrow = lane & 15;
    const int lco  = (lane >> 4) << 3;

    float acc[2][NT][4];
    #pragma unroll
    for (int i = 0; i < 2; i++)
        #pragma unroll
        for (int j = 0; j < NT; j++)
            #pragma unroll
            for (int q = 0; q < 4; q++) acc[i][j][q] = 0.0f;

    for (int kk = kbeg; kk < kbeg + kpart; kk += BK) {
        // load A tile (128x32 bf16) via 16B chunks
        #pragma unroll
        for (int i = 0; i < BM * BK / 8; i += 256) {
            int c = tid + i, r = c >> 2, off = (c & 3) * 8;
            *(uint4*)(&As[r * LDS + off]) =
                *(const uint4*)(A + (size_t)(m0 + r) * K + kk + off);
        }
        // load B tile (BNx32)
        #pragma unroll
        for (int i = 0; i < BN * BK / 8; i += 256) {
            int c = tid + i, r = c >> 2, off = (c & 3) * 8;
            *(uint4*)(&Bs[r * LDS + off]) =
                *(const uint4*)(B + (size_t)(n0 + r) * K + kk + off);
        }
        __syncthreads();
        #pragma unroll
        for (int ks = 0; ks < 2; ks++) {
            uint32_t a[2][4];
            #pragma unroll
            for (int mt = 0; mt < 2; mt++)
                ldsm_x4(a[mt][0], a[mt][1], a[mt][2], a[mt][3],
                        &As[(wm * 32 + mt * 16 + lrow) * LDS + ks * 16 + lco]);
            uint32_t bb[NT][2];
            #pragma unroll
            for (int p = 0; p < NP; p++) {
                uint32_t r0, r1, r2, r3;
                ldsm_x4(r0, r1, r2, r3,
                        &Bs[(wn * WN + p * 16 + lrow) * LDS + ks * 16 + lco]);
                bb[2 * p][0] = r0; bb[2 * p][1] = r2;
                bb[2 * p + 1][0] = r1; bb[2 * p + 1][1] = r3;
            }
            #pragma unroll
            for (int mt = 0; mt < 2; mt++)
                #pragma unroll
                for (int nt = 0; nt < NT; nt++)
                    mma_bf16(acc[mt][nt], a[mt], bb[nt]);
        }
        __syncthreads();
    }

    // epilogue
    #pragma unroll
    for (int mt = 0; mt < 2; mt++) {
        int r0 = m0 + wm * 32 + mt * 16 + (lane >> 2);
        float g0 = 0.0f, g1 = 0.0f;
        if (EPI == 1) { g0 = gate[r0]; g1 = gate[r0 + 8]; }
        #pragma unroll
        for (int nt = 0; nt < NT; nt++) {
            int cc = n0 + wn * WN + nt * 8 + (lane & 3) * 2;
            size_t o0 = (size_t)r0 * N + cc;
            size_t o1 = (size_t)(r0 + 8) * N + cc;
            if (EPI == 0) {
                Cout[o0]     = acc[mt][nt][0];
                Cout[o0 + 1] = acc[mt][nt][1];
                Cout[o1]     = acc[mt][nt][2];
                Cout[o1 + 1] = acc[mt][nt][3];
            } else {
                Cout[o0]     = hs[o0]     + g0 * acc[mt][nt][0];
                Cout[o0 + 1] = hs[o0 + 1] + g0 * acc[mt][nt][1];
                Cout[o1]     = hs[o1]     + g1 * acc[mt][nt][2];
                Cout[o1 + 1] = hs[o1 + 1] + g1 * acc[mt][nt][3];
            }
        }
    }
}

// ---------------- SIMT GEMM (small ops): C = A @ B^T ----------------
template<int BM, int BN, int BK, int TM, int TN>
__global__ void gemm_nt(const float* __restrict__ A, const float* __restrict__ B,
                        float* __restrict__ C, int M, int N, int Kd) {
    __shared__ float As[BK][BM + 4];
    __shared__ float Bs[BK][BN + 4];
    constexpr int TX = BN / TN, TY = BM / TM, NTHR = TX * TY;
    const int tid = threadIdx.x;
    const int tx = tid % TX, ty = tid / TX;
    const int m0 = blockIdx.y * BM, n0 = blockIdx.x * BN;

    float acc[TM][TN];
    #pragma unroll
    for (int i = 0; i < TM; i++)
        #pragma unroll
        for (int j = 0; j < TN; j++) acc[i][j] = 0.0f;

    for (int k0 = 0; k0 < Kd; k0 += BK) {
        for (int e = tid; e < BM * BK; e += NTHR) {
            int r = e / BK, c = e % BK;
            As[c][r] = (m0 + r < M) ? A[(size_t)(m0 + r) * Kd + k0 + c] : 0.0f;
        }
        for (int e = tid; e < BN * BK; e += NTHR) {
            int r = e / BK, c = e % BK;
            Bs[c][r] = (n0 + r < N) ? B[(size_t)(n0 + r) * Kd + k0 + c] : 0.0f;
        }
        __syncthreads();
        #pragma unroll
        for (int kk = 0; kk < BK; kk++) {
            float a[TM], b[TN];
            #pragma unroll
            for (int i = 0; i < TM; i++) a[i] = As[kk][ty * TM + i];
            #pragma unroll
            for (int j = 0; j < TN; j++) b[j] = Bs[kk][tx * TN + j];
            #pragma unroll
            for (int i = 0; i < TM; i++)
                #pragma unroll
                for (int j = 0; j < TN; j++) acc[i][j] += a[i] * b[j];
        }
        __syncthreads();
    }
    #pragma unroll
    for (int i = 0; i < TM; i++) {
        int gm = m0 + ty * TM + i;
        if (gm >= M) continue;
        #pragma unroll
        for (int j = 0; j < TN; j++) {
            int gn = n0 + tx * TN + j;
            if (gn < N) C[(size_t)gm * N + gn] = acc[i][j];
        }
    }
}

// ---------------- fp32 -> bf16 convert ----------------
__global__ void k_cvt(const float* __restrict__ in, bf16* __restrict__ out, int n4) {
    int i = blockIdx.x * 256 + threadIdx.x;
    if (i >= n4) return;
    float4 f = ((const float4*)in)[i];
    ((__nv_bfloat162*)out)[2 * i]     = __floats2bfloat162_rn(f.x, f.y);
    ((__nv_bfloat162*)out)[2 * i + 1] = __floats2bfloat162_rn(f.z, f.w);
}

// ---------------- fused: hs -> bf16 copy + per-token log1p(var) ----------------
__global__ void k_prep_h(const float* __restrict__ hs) {
    __shared__ float sh1[256], sh2[256];
    const int t = blockIdx.x, tid = threadIdx.x;
    const float4* row = (const float4*)(hs + (size_t)t * HID);
    __nv_bfloat162* orow = (__nv_bfloat162*)(g_Hb + (size_t)t * HID);
    float s = 0.0f, s2 = 0.0f;
    #pragma unroll
    for (int i = 0; i < HID / 4 / 256; i++) {
        int c = tid + i * 256;
        float4 f = row[c];
        s += f.x + f.y + f.z + f.w;
        s2 += f.x * f.x + f.y * f.y + f.z * f.z + f.w * f.w;
        orow[2 * c]     = __floats2bfloat162_rn(f.x, f.y);
        orow[2 * c + 1] = __floats2bfloat162_rn(f.z, f.w);
    }
    sh1[tid] = s; sh2[tid] = s2;
    __syncthreads();
    for (int off = 128; off > 0; off >>= 1) {
        if (tid < off) { sh1[tid] += sh1[tid + off]; sh2[tid] += sh2[tid + off]; }
        __syncthreads();
    }
    if (tid == 0) {
        float mean = sh1[0] * (1.0f / HID);
        float var  = sh2[0] * (1.0f / HID) - mean * mean;
        g_logvar[t] = log1pf(var);
    }
}

__global__ void k_mean(int T) {
    __shared__ float sh[256];
    float s = 0.0f;
    for (int i = threadIdx.x; i < T; i += 256) s += g_logvar[i];
    sh[threadIdx.x] = s;
    __syncthreads();
    for (int off = 128; off > 0; off >>= 1) {
        if (threadIdx.x < off) sh[threadIdx.x] += sh[threadIdx.x + off];
        __syncthreads();
    }
    if (threadIdx.x == 0) g_mean[0] = sh[0] / (float)T;
}

// ---------------- learned[t] + gate[t] ----------------
__global__ void k_learned(const float* __restrict__ bu1, const float* __restrict__ wu2,
                          const float* __restrict__ bu2, const float* __restrict__ gw1,
                          const float* __restrict__ gb) {
    __shared__ float sh[256];
    const int t = blockIdx.x, tid = threadIdx.x;
    const float* yrow = g_Y + (size_t)t * HU;
    float s = 0.0f;
    #pragma unroll
    for (int i = 0; i < HU / 256; i++) {
        int j = tid + i * 256;
        s += gelu_tanh(yrow[j] + bu1[j]) * wu2[j];
    }
    sh[tid] = s;
    __syncthreads();
    for (int off = 128; off > 0; off >>= 1) {
        if (tid < off) sh[tid] += sh[tid + off];
        __syncthreads();
    }
    if (tid == 0) {
        float learned = sh[0] + bu2[0];
        float nv = g_logvar[t] / (g_mean[0] + 1e-6f);
        float u = fminf(fmaxf(nv * 0.5f + sigmoidf(learned) * 2.5f, 0.0f), 5.0f);
        float un = fminf(fmaxf((u - 0.5f) * (1.0f / 1.5f), 0.0f), 1.0f);
        float g = sigmoidf(gw1[0] * un + gb[0]);
        g_gate[t] = (g < 0.05f) ? 0.0f : g;
    }
}

// ---------------- reduce split-K partials ----------------
__global__ void k_reduceQ(int T) {
    int i = blockIdx.x * 256 + threadIdx.x;     // float4 index
    if (i >= T * BOT / 4) return;
    float4 a = ((const float4*)g_Qpart[0])[i];
    float4 b = ((const float4*)g_Qpart[1])[i];
    float4 c = ((const float4*)g_Qpart[2])[i];
    float4 d = ((const float4*)g_Qpart[3])[i];
    float4 r; r.x = a.x + b.x + c.x + d.x; r.y = a.y + b.y + c.y + d.y;
    r.z = a.z + b.z + c.z + d.z; r.w = a.w + b.w + c.w + d.w;
    ((float4*)g_Q)[i] = r;
    ((__nv_bfloat162*)g_Qb)[2 * i]     = __floats2bfloat162_rn(r.x, r.y);
    ((__nv_bfloat162*)g_Qb)[2 * i + 1] = __floats2bfloat162_rn(r.z, r.w);
}

__global__ void k_reduceAD() {
    int i = blockIdx.x * 256 + threadIdx.x;     // float4 index
    if (i >= NSLOT * VB / 4) return;
    float4 r = ((const float4*)g_ADpart[0])[i];
    #pragma unroll
    for (int z = 1; z < 8; z++) {
        float4 p = ((const float4*)g_ADpart[z])[i];
        r.x += p.x; r.y += p.y; r.z += p.z; r.w += p.w;
    }
    ((float4*)g_auxdown)[i] = r;
}

// ---------------- Mslot = rk @ Wr  [NSLOT x BOT] -> bf16 ----------------
__global__ void k_mslot(const float* __restrict__ Wr) {
    int idx = blockIdx.x * 256 + threadIdx.x;   // n*64 + c
    int n = idx >> 6, c = idx & 63;
    float s = 0.0f;
    #pragma unroll
    for (int r = 0; r < RDIM; r++) s += g_rk[n * RDIM + r] * Wr[r * BOT + c];
    g_Mslotb[idx] = __float2bfloat16(s);
}

// ---------------- top-k + attention + bottleneck gather ----------------
__global__ void k_topk(const float* __restrict__ aux_keys,
                       const float* __restrict__ log_rel) {
    __shared__ float s_w[8][TOPK];
    __shared__ int   s_idx[8][TOPK];
    const int tid = threadIdx.x, w = tid >> 5, lane = tid & 31;
    const int t = blockIdx.x * 8 + w;
    const float inv_sqrt_r = 0.14433756729740643f;   // 1/sqrt(48)

    float v[32];
    const float* srow = g_scores + (size_t)t * NSLOT;
    #pragma unroll
    for (int i = 0; i < 32; i++)
        v[i] = srow[i * 32 + lane] * inv_sqrt_r + __ldg(&log_rel[i * 32 + lane]);

    for (int sel = 0; sel < TOPK; sel++) {
        float m = -INFINITY; int mi = NSLOT;
        #pragma unroll
        for (int i = 0; i < 32; i++)
            if (v[i] > m) { m = v[i]; mi = i * 32 + lane; }
        #pragma unroll
        for (int off = 16; off >= 1; off >>= 1) {
            float om = __shfl_xor_sync(0xffffffffu, m, off);
            int   omi = __shfl_xor_sync(0xffffffffu, mi, off);
            if (om > m || (om == m && omi < mi)) { m = om; mi = omi; }
        }
        if ((mi & 31) == lane) v[mi >> 5] = -INFINITY;
        if (lane == 0) s_idx[w][sel] = mi;
    }
    __syncwarp();

    if (lane < TOPK) {
        int idx = s_idx[w][lane];
        const float* qr = &g_Q[(size_t)t * BOT];
        const float* kr = &aux_keys[(size_t)idx * BOT];
        float dot = 0.0f;
        #pragma unroll
        for (int c = 0; c < BOT; c++) dot += qr[c] * kr[c];
        float a = dot * 0.125f + log_rel[idx];
        float mx = a;
        #pragma unroll
        for (int off = 4; off >= 1; off >>= 1)
            mx = fmaxf(mx, __shfl_xor_sync(0xffu, mx, off, 8));
        float e = expf(a - mx);
        float se = e;
        #pragma unroll
        for (int off = 4; off >= 1; off >>= 1)
            se += __shfl_xor_sync(0xffu, se, off, 8);
        s_w[w][lane] = e / se;
    }
    __syncwarp();

    int   idxs[TOPK]; float ws[TOPK];
    #pragma unroll
    for (int k = 0; k < TOPK; k++) { idxs[k] = s_idx[w][k]; ws[k] = s_w[w][k]; }
    #pragma unroll
    for (int j = 0; j < VB / 32; j++) {
        int col = lane + j * 32;
        float acc = 0.0f;
        #pragma unroll
        for (int k = 0; k < TOPK; k++)
            acc += ws[k] * g_auxdown[(size_t)idxs[k] * VB + col];
        g_downb[(size_t)t * VB + col] = __float2bfloat16(acc);
    }
}

// ---------------- launch ----------------
extern "C" void kernel_launch(void* const* d_in, const int* in_sizes, int n_in,
                              void* d_out, int out_size) {
    const float* hs       = (const float*)d_in[0];
    const float* Wq       = (const float*)d_in[1];
    const float* Wr       = (const float*)d_in[2];
    const float* aux_keys = (const float*)d_in[3];
    const float* aux_vals = (const float*)d_in[4];
    const float* Wvd      = (const float*)d_in[5];
    const float* Wvu      = (const float*)d_in[6];
    const float* Wu1      = (const float*)d_in[7];
    const float* bu1      = (const float*)d_in[8];
    const float* Wu2      = (const float*)d_in[9];
    const float* bu2      = (const float*)d_in[10];
    const float* gw1      = (const float*)d_in[11];
    const float* gb       = (const float*)d_in[12];
    const float* log_rel  = (const float*)d_in[13];
    float* out = (float*)d_out;

    const int T = in_sizes[0] / HID;   // 4096

    bf16 *pHb, *pWu1b, *pWqb, *pAvalb, *pWvdb, *pWvub, *pQb, *pMslotb, *pDownb;
    float *pY, *pQpart, *pQ, *pRk, *pScores, *pADpart, *pAD;
    cudaGetSymbolAddress((void**)&pHb, g_Hb);
    cudaGetSymbolAddress((void**)&pWu1b, g_Wu1b);
    cudaGetSymbolAddress((void**)&pWqb, g_Wqb);
    cudaGetSymbolAddress((void**)&pAvalb, g_Avalb);
    cudaGetSymbolAddress((void**)&pWvdb, g_Wvdb);
    cudaGetSymbolAddress((void**)&pWvub, g_Wvub);
    cudaGetSymbolAddress((void**)&pQb, g_Qb);
    cudaGetSymbolAddress((void**)&pMslotb, g_Mslotb);
    cudaGetSymbolAddress((void**)&pDownb, g_downb);
    cudaGetSymbolAddress((void**)&pY, g_Y);
    cudaGetSymbolAddress((void**)&pQpart, g_Qpart);
    cudaGetSymbolAddress((void**)&pQ, g_Q);
    cudaGetSymbolAddress((void**)&pRk, g_rk);
    cudaGetSymbolAddress((void**)&pScores, g_scores);
    cudaGetSymbolAddress((void**)&pADpart, g_ADpart);
    cudaGetSymbolAddress((void**)&pAD, g_auxdown);

    float *pGate;
    cudaGetSymbolAddress((void**)&pGate, g_gate);

    // weight conversions to bf16
    k_cvt<<<(HU * HID / 4 + 255) / 256, 256>>>(Wu1, pWu1b, HU * HID / 4);
    k_cvt<<<(BOT * HID / 4 + 255) / 256, 256>>>(Wq, pWqb, BOT * HID / 4);
    k_cvt<<<(NSLOT * HID / 4 + 255) / 256, 256>>>(aux_vals, pAvalb, NSLOT * HID / 4);
    k_cvt<<<(VB * HID / 4 + 255) / 256, 256>>>(Wvd, pWvdb, VB * HID / 4);
    k_cvt<<<(HID * VB / 4 + 255) / 256, 256>>>(Wvu, pWvub, HID * VB / 4);

    // H -> bf16 + per-token log1p(var); global mean
    k_prep_h<<<T, 256>>>(hs);
    k_mean<<<1, 256>>>(T);

    // Y = H @ Wu1^T   [T x 1024], K=4096
    mma_nt<128, 0><<<dim3(HU / 128, T / 128, 1), 256>>>(pHb, pWu1b, pY, T, HU, HID, nullptr, nullptr);
    // learned + gate
    k_learned<<<T, 256>>>(bu1, Wu2, bu2, gw1, gb);

    // Q = H @ Wq^T    [T x 64], split-K 4 + reduce
    mma_nt<64, 0><<<dim3(1, T / 128, 4), 256>>>(pHb, pWqb, pQpart, T, BOT, HID, nullptr, nullptr);
    k_reduceQ<<<(T * BOT / 4 + 255) / 256, 256>>>(T);

    // rk = aux_keys @ Wr^T  [1024 x 48] (SIMT, tiny), then Mslot = rk @ Wr -> bf16
    gemm_nt<64, 64, 16, 4, 4><<<dim3(1, NSLOT / 64), 256>>>(aux_keys, Wr, pRk, NSLOT, RDIM, BOT);
    k_mslot<<<NSLOT * BOT / 256, 256>>>(Wr);

    // scores = Q @ Mslot^T  [T x 1024], K=64
    mma_nt<128, 0><<<dim3(NSLOT / 128, T / 128, 1), 256>>>(pQb, pMslotb, pScores, T, NSLOT, BOT, nullptr, nullptr);

    // aux_down = aux_values @ Wvd^T  [1024 x 256], split-K 8 + reduce
    mma_nt<128, 0><<<dim3(VB / 128, NSLOT / 128, 8), 256>>>(pAvalb, pWvdb, pADpart, NSLOT, VB, HID, nullptr, nullptr);
    k_reduceAD<<<(NSLOT * VB / 4 + 255) / 256, 256>>>();

    // top-8 + attention + gather -> g_downb (bf16)
    k_topk<<<T / 8, 256>>>(aux_keys, log_rel);

    // out = hs + gate * (down @ Wvu^T)   [T x 4096], K=256
    mma_nt<128, 1><<<dim3(HID / 128, T / 128, 1), 256>>>(pDownb, pWvub, out, T, HID, VB, hs, pGate);
}

// round 3
// speedup vs baseline: 1.2359x; 1.2359x over previous
#include <cuda_runtime.h>
#include <cuda_bf16.h>
#include <math.h>
#include <stdint.h>

#define HID   4096
#define BOT   64
#define RDIM  48
#define NSLOT 1024
#define TOPK  8
#define VB    256
#define HU    1024
#define TMAX  4096

typedef __nv_bfloat16 bf16;

// ---------------- static scratch ----------------
__device__ bf16  g_Hb[(size_t)TMAX * HID];        // 32 MB
__device__ bf16  g_Wu1b[HU * HID];                // 8 MB
__device__ bf16  g_Wqb[BOT * HID];
__device__ bf16  g_Avalb[NSLOT * HID];            // 8 MB
__device__ bf16  g_Wvdb[VB * HID];
__device__ bf16  g_Wvub[HID * VB];
__device__ float g_Qpart[4][TMAX * BOT];          // 4 MB
__device__ float g_Q[TMAX * BOT];
__device__ bf16  g_Qb[TMAX * BOT];
__device__ float g_rk[NSLOT * RDIM];
__device__ bf16  g_Mslotb[NSLOT * BOT];
__device__ float g_scores[(size_t)TMAX * NSLOT];  // 16 MB
__device__ float g_ADpart[8][NSLOT * VB];         // 8 MB
__device__ float g_auxdown[NSLOT * VB];
__device__ bf16  g_downb[TMAX * VB];
__device__ float g_lpart[TMAX * 8];               // Y-epilogue partial sums
__device__ float g_logvar[TMAX];
__device__ float g_gate[TMAX];
__device__ float g_mean[1];

__device__ __forceinline__ float gelu_tanh(float x) {
    float x3 = x * x * x;
    return 0.5f * x * (1.0f + tanhf(0.7978845608028654f * (x + 0.044715f * x3)));
}
__device__ __forceinline__ float sigmoidf(float x) { return 1.0f / (1.0f + expf(-x)); }

// ---------------- ldmatrix / mma / cp.async helpers ----------------
__device__ __forceinline__ void ldsm_x4(uint32_t& r0, uint32_t& r1, uint32_t& r2, uint32_t& r3,
                                        const bf16* p) {
    uint32_t addr = (uint32_t)__cvta_generic_to_shared(p);
    asm volatile("ldmatrix.sync.aligned.m8n8.x4.shared.b16 {%0,%1,%2,%3}, [%4];"
                 : "=r"(r0), "=r"(r1), "=r"(r2), "=r"(r3) : "r"(addr));
}
__device__ __forceinline__ void mma_bf16(float* c, const uint32_t* a, const uint32_t* b) {
    asm volatile(
        "mma.sync.aligned.m16n8k16.row.col.f32.bf16.bf16.f32 "
        "{%0,%1,%2,%3}, {%4,%5,%6,%7}, {%8,%9}, {%0,%1,%2,%3};"
        : "+f"(c[0]), "+f"(c[1]), "+f"(c[2]), "+f"(c[3])
        : "r"(a[0]), "r"(a[1]), "r"(a[2]), "r"(a[3]), "r"(b[0]), "r"(b[1]));
}
__device__ __forceinline__ void cp16(bf16* s, const bf16* g) {
    uint32_t saddr = (uint32_t)__cvta_generic_to_shared(s);
    asm volatile("cp.async.cg.shared.global [%0], [%1], 16;" :: "r"(saddr), "l"(g));
}
__device__ __forceinline__ void cp_commit() { asm volatile("cp.async.commit_group;"); }
template<int N> __device__ __forceinline__ void cp_wait() {
    asm volatile("cp.async.wait_group %0;" :: "n"(N));
}

// ---------------- pipelined tensor-core GEMM: C[M,N] = A[M,K] @ B[N,K]^T ----------
// BM=128, BK=64, 2-stage cp.async double buffer, 256 threads (warps 4m x 2n).
// gridDim.z = deterministic split-K (partials at C + z*M*N).
// EPI 0: fp32 store. EPI 1: C = aux0(hs) + aux1(gate)[row]*acc.
// EPI 2: fused gelu(acc+bu1)*wu2 row-reduction -> C used as lpart[M][gridDim.x].
template<int BN, int EPI>
__global__ void mma_pipe(const bf16* __restrict__ A, const bf16* __restrict__ B,
                         float* __restrict__ C, int M, int N, int K,
                         const float* __restrict__ aux0, const float* __restrict__ aux1) {
    constexpr int BM = 128, BK = 64, LDA = 72;       // 144B rows (16B aligned, 4-bank skew)
    constexpr int WN = BN / 2, NT = WN / 8, NP = NT / 2;
    constexpr int ACH = BM * BK / 8;                 // 16B chunks in A tile
    constexpr int BCH = BN * BK / 8;
    extern __shared__ bf16 sm[];
    bf16* As = sm;                                   // 2 stages of BM*LDA
    bf16* Bs = sm + 2 * BM * LDA;

    __shared__ float s_row[BM][2];
    __shared__ float s_bu1[BN];
    __shared__ float s_wu2[BN];

    const int tid = threadIdx.x, lane = tid & 31, w = tid >> 5;
    const int wm = w & 3, wn = w >> 2;
    const int m0 = blockIdx.y * BM, n0 = blockIdx.x * BN;
    const int kpart = K / gridDim.z;
    const int kbeg = blockIdx.z * kpart;
    const int ntiles = kpart / BK;
    float* Cout = C + (size_t)blockIdx.z * M * N;

    if (EPI == 2) {
        for (int i = tid; i < BN; i += 256) {
            s_bu1[i] = aux0[n0 + i];
            s_wu2[i] = aux1[n0 + i];
        }
    }

    const int lrow = lane & 15;
    const int lco  = (lane >> 4) << 3;

    float acc[2][NT][4];
    #pragma unroll
    for (int i = 0; i < 2; i++)
        #pragma unroll
        for (int j = 0; j < NT; j++)
            #pragma unroll
            for (int q = 0; q < 4; q++) acc[i][j][q] = 0.0f;

    // ---- issue stage 0 ----
    {
        const int kk = kbeg;
        #pragma unroll
        for (int i = tid; i < ACH; i += 256) {
            int r = i >> 3, off = (i & 7) * 8;
            cp16(&As[r * LDA + off], A + (size_t)(m0 + r) * K + kk + off);
        }
        #pragma unroll
        for (int i = tid; i < BCH; i += 256) {
            int r = i >> 3, off = (i & 7) * 8;
            cp16(&Bs[r * LDA + off], B + (size_t)(n0 + r) * K + kk + off);
        }
        cp_commit();
    }

    for (int kt = 0; kt < ntiles; kt++) {
        if (kt + 1 < ntiles) {
            const int st = (kt + 1) & 1;
            const int kk = kbeg + (kt + 1) * BK;
            bf16* Ad = As + st * BM * LDA;
            bf16* Bd = Bs + st * BN * LDA;
            #pragma unroll
            for (int i = tid; i < ACH; i += 256) {
                int r = i >> 3, off = (i & 7) * 8;
                cp16(&Ad[r * LDA + off], A + (size_t)(m0 + r) * K + kk + off);
            }
            #pragma unroll
            for (int i = tid; i < BCH; i += 256) {
                int r = i >> 3, off = (i & 7) * 8;
                cp16(&Bd[r * LDA + off], B + (size_t)(n0 + r) * K + kk + off);
            }
            cp_commit();
            cp_wait<1>();
        } else {
            cp_wait<0>();
        }
        __syncthreads();

        const bf16* Ac = As + (kt & 1) * BM * LDA;
        const bf16* Bc = Bs + (kt & 1) * BN * LDA;
        #pragma unroll
        for (int ks = 0; ks < 4; ks++) {
            uint32_t a[2][4];
            #pragma unroll
            for (int mt = 0; mt < 2; mt++)
                ldsm_x4(a[mt][0], a[mt][1], a[mt][2], a[mt][3],
                        &Ac[(wm * 32 + mt * 16 + lrow) * LDA + ks * 16 + lco]);
            uint32_t bb[NT][2];
            #pragma unroll
            for (int p = 0; p < NP; p++) {
                uint32_t r0, r1, r2, r3;
                ldsm_x4(r0, r1, r2, r3,
                        &Bc[(wn * WN + p * 16 + lrow) * LDA + ks * 16 + lco]);
                bb[2 * p][0] = r0; bb[2 * p][1] = r2;
                bb[2 * p + 1][0] = r1; bb[2 * p + 1][1] = r3;
            }
            #pragma unroll
            for (int mt = 0; mt < 2; mt++)
                #pragma unroll
                for (int nt = 0; nt < NT; nt++)
                    mma_bf16(acc[mt][nt], a[mt], bb[nt]);
        }
        __syncthreads();
    }

    if (EPI == 2) {
        // fused gelu(y+bu1)*wu2 row-reduction
        float rs[2][2];
        rs[0][0] = rs[0][1] = rs[1][0] = rs[1][1] = 0.0f;
        #pragma unroll
        for (int mt = 0; mt < 2; mt++) {
            #pragma unroll
            for (int nt = 0; nt < NT; nt++) {
                int lc = wn * WN + nt * 8 + (lane & 3) * 2;
                float b0 = s_bu1[lc], b1 = s_bu1[lc + 1];
                float w0 = s_wu2[lc], w1 = s_wu2[lc + 1];
                rs[mt][0] += gelu_tanh(acc[mt][nt][0] + b0) * w0
                           + gelu_tanh(acc[mt][nt][1] + b1) * w1;
                rs[mt][1] += gelu_tanh(acc[mt][nt][2] + b0) * w0
                           + gelu_tanh(acc[mt][nt][3] + b1) * w1;
            }
        }
        #pragma unroll
        for (int mt = 0; mt < 2; mt++)
            #pragma unroll
            for (int h = 0; h < 2; h++) {
                rs[mt][h] += __shfl_xor_sync(0xffffffffu, rs[mt][h], 1);
                rs[mt][h] += __shfl_xor_sync(0xffffffffu, rs[mt][h], 2);
            }
        if ((lane & 3) == 0) {
            #pragma unroll
            for (int mt = 0; mt < 2; mt++)
                #pragma unroll
                for (int h = 0; h < 2; h++)
                    s_row[wm * 32 + mt * 16 + (lane >> 2) + h * 8][wn] = rs[mt][h];
        }
        __syncthreads();
        if (tid < BM)
            Cout[(size_t)(m0 + tid) * gridDim.x + blockIdx.x] =
                s_row[tid][0] + s_row[tid][1];
        return;
    }

    #pragma unroll
    for (int mt = 0; mt < 2; mt++) {
        int r0 = m0 + wm * 32 + mt * 16 + (lane >> 2);
        float g0 = 0.0f, g1 = 0.0f;
        if (EPI == 1) { g0 = aux1[r0]; g1 = aux1[r0 + 8]; }
        #pragma unroll
        for (int nt = 0; nt < NT; nt++) {
            int cc = n0 + wn * WN + nt * 8 + (lane & 3) * 2;
            size_t o0 = (size_t)r0 * N + cc;
            size_t o1 = (size_t)(r0 + 8) * N + cc;
            if (EPI == 0) {
                Cout[o0]     = acc[mt][nt][0];
                Cout[o0 + 1] = acc[mt][nt][1];
                Cout[o1]     = acc[mt][nt][2];
                Cout[o1 + 1] = acc[mt][nt][3];
            } else {
                Cout[o0]     = aux0[o0]     + g0 * acc[mt][nt][0];
                Cout[o0 + 1] = aux0[o0 + 1] + g0 * acc[mt][nt][1];
                Cout[o1]     = aux0[o1]     + g1 * acc[mt][nt][2];
                Cout[o1 + 1] = aux0[o1 + 1] + g1 * acc[mt][nt][3];
            }
        }
    }
}

// ---------------- SIMT GEMM for tiny rk op ----------------
template<int BM, int BN, int BK, int TM, int TN>
__global__ void gemm_nt(const float* __restrict__ A, const float* __restrict__ B,
                        float* __restrict__ C, int M, int N, int Kd) {
    __shared__ float As[BK][BM + 4];
    __shared__ float Bs[BK][BN + 4];
    constexpr int TX = BN / TN, TY = BM / TM, NTHR = TX * TY;
    const int tid = threadIdx.x;
    const int tx = tid % TX, ty = tid / TX;
    const int m0 = blockIdx.y * BM, n0 = blockIdx.x * BN;
    float acc[TM][TN];
    #pragma unroll
    for (int i = 0; i < TM; i++)
        #pragma unroll
        for (int j = 0; j < TN; j++) acc[i][j] = 0.0f;
    for (int k0 = 0; k0 < Kd; k0 += BK) {
        for (int e = tid; e < BM * BK; e += NTHR) {
            int r = e / BK, c = e % BK;
            As[c][r] = (m0 + r < M) ? A[(size_t)(m0 + r) * Kd + k0 + c] : 0.0f;
        }
        for (int e = tid; e < BN * BK; e += NTHR) {
            int r = e / BK, c = e % BK;
            Bs[c][r] = (n0 + r < N) ? B[(size_t)(n0 + r) * Kd + k0 + c] : 0.0f;
        }
        __syncthreads();
        #pragma unroll
        for (int kk = 0; kk < BK; kk++) {
            float a[TM], b[TN];
            #pragma unroll
            for (int i = 0; i < TM; i++) a[i] = As[kk][ty * TM + i];
            #pragma unroll
            for (int j = 0; j < TN; j++) b[j] = Bs[kk][tx * TN + j];
            #pragma unroll
            for (int i = 0; i < TM; i++)
                #pragma unroll
                for (int j = 0; j < TN; j++) acc[i][j] += a[i] * b[j];
        }
        __syncthreads();
    }
    #pragma unroll
    for (int i = 0; i < TM; i++) {
        int gm = m0 + ty * TM + i;
        if (gm >= M) continue;
        #pragma unroll
        for (int j = 0; j < TN; j++) {
            int gn = n0 + tx * TN + j;
            if (gn < N) C[(size_t)gm * N + gn] = acc[i][j];
        }
    }
}

// ---------------- fp32 -> bf16 convert (4x ILP) ----------------
__global__ void k_cvt4(const float* __restrict__ in, bf16* __restrict__ out, int n4) {
    int base = (blockIdx.x * 256 + threadIdx.x) * 4;
    float4 f[4];
    #pragma unroll
    for (int j = 0; j < 4; j++) {
        int i = base + j;
        if (i < n4) f[j] = ((const float4*)in)[i];
    }
    #pragma unroll
    for (int j = 0; j < 4; j++) {
        int i = base + j;
        if (i < n4) {
            ((__nv_bfloat162*)out)[2 * i]     = __floats2bfloat162_rn(f[j].x, f[j].y);
            ((__nv_bfloat162*)out)[2 * i + 1] = __floats2bfloat162_rn(f[j].z, f[j].w);
        }
    }
}

// ---------------- fused: hs -> bf16 + per-token log1p(var) ----------------
__global__ void k_prep_h(const float* __restrict__ hs) {
    __shared__ float sh1[256], sh2[256];
    const int t = blockIdx.x, tid = threadIdx.x;
    const float4* row = (const float4*)(hs + (size_t)t * HID);
    __nv_bfloat162* orow = (__nv_bfloat162*)(g_Hb + (size_t)t * HID);
    float s = 0.0f, s2 = 0.0f;
    float4 f[4];
    #pragma unroll
    for (int i = 0; i < 4; i++) f[i] = row[tid + i * 256];
    #pragma unroll
    for (int i = 0; i < 4; i++) {
        int c = tid + i * 256;
        s += f[i].x + f[i].y + f[i].z + f[i].w;
        s2 += f[i].x * f[i].x + f[i].y * f[i].y + f[i].z * f[i].z + f[i].w * f[i].w;
        orow[2 * c]     = __floats2bfloat162_rn(f[i].x, f[i].y);
        orow[2 * c + 1] = __floats2bfloat162_rn(f[i].z, f[i].w);
    }
    sh1[tid] = s; sh2[tid] = s2;
    __syncthreads();
    for (int off = 128; off > 0; off >>= 1) {
        if (tid < off) { sh1[tid] += sh1[tid + off]; sh2[tid] += sh2[tid + off]; }
        __syncthreads();
    }
    if (tid == 0) {
        float mean = sh1[0] * (1.0f / HID);
        float var  = sh2[0] * (1.0f / HID) - mean * mean;
        g_logvar[t] = log1pf(var);
    }
}

__global__ void k_mean(int T) {
    __shared__ float sh[256];
    float s = 0.0f;
    for (int i = threadIdx.x; i < T; i += 256) s += g_logvar[i];
    sh[threadIdx.x] = s;
    __syncthreads();
    for (int off = 128; off > 0; off >>= 1) {
        if (threadIdx.x < off) sh[threadIdx.x] += sh[threadIdx.x + off];
        __syncthreads();
    }
    if (threadIdx.x == 0) g_mean[0] = sh[0] / (float)T;
}

// ---------------- gate from lpart + variance ----------------
__global__ void k_gate(const float* __restrict__ bu2, const float* __restrict__ gw1,
                       const float* __restrict__ gb) {
    int t = blockIdx.x * 256 + threadIdx.x;
    float s = 0.0f;
    #pragma unroll
    for (int i = 0; i < 8; i++) s += g_lpart[t * 8 + i];
    float learned = s + bu2[0];
    float nv = g_logvar[t] / (g_mean[0] + 1e-6f);
    float u = fminf(fmaxf(nv * 0.5f + sigmoidf(learned) * 2.5f, 0.0f), 5.0f);
    float un = fminf(fmaxf((u - 0.5f) * (1.0f / 1.5f), 0.0f), 1.0f);
    float g = sigmoidf(gw1[0] * un + gb[0]);
    g_gate[t] = (g < 0.05f) ? 0.0f : g;
}

// ---------------- split-K reductions ----------------
__global__ void k_reduceQ(int T) {
    int i = blockIdx.x * 256 + threadIdx.x;
    if (i >= T * BOT / 4) return;
    float4 a = ((const float4*)g_Qpart[0])[i];
    float4 b = ((const float4*)g_Qpart[1])[i];
    float4 c = ((const float4*)g_Qpart[2])[i];
    float4 d = ((const float4*)g_Qpart[3])[i];
    float4 r; r.x = a.x + b.x + c.x + d.x; r.y = a.y + b.y + c.y + d.y;
    r.z = a.z + b.z + c.z + d.z; r.w = a.w + b.w + c.w + d.w;
    ((float4*)g_Q)[i] = r;
    ((__nv_bfloat162*)g_Qb)[2 * i]     = __floats2bfloat162_rn(r.x, r.y);
    ((__nv_bfloat162*)g_Qb)[2 * i + 1] = __floats2bfloat162_rn(r.z, r.w);
}

__global__ void k_reduceAD() {
    int i = blockIdx.x * 256 + threadIdx.x;
    if (i >= NSLOT * VB / 4) return;
    float4 r = ((const float4*)g_ADpart[0])[i];
    #pragma unroll
    for (int z = 1; z < 8; z++) {
        float4 p = ((const float4*)g_ADpart[z])[i];
        r.x += p.x; r.y += p.y; r.z += p.z; r.w += p.w;
    }
    ((float4*)g_auxdown)[i] = r;
}

// ---------------- Mslot = rk @ Wr -> bf16 ----------------
__global__ void k_mslot(const float* __restrict__ Wr) {
    int idx = blockIdx.x * 256 + threadIdx.x;
    int n = idx >> 6, c = idx & 63;
    float s = 0.0f;
    #pragma unroll
    for (int r = 0; r < RDIM; r++) s += g_rk[n * RDIM + r] * Wr[r * BOT + c];
    g_Mslotb[idx] = __float2bfloat16(s);
}

// ---------------- top-k + attention + bottleneck gather ----------------
__global__ void k_topk(const float* __restrict__ aux_keys,
                       const float* __restrict__ log_rel) {
    __shared__ float s_w[8][TOPK];
    __shared__ int   s_idx[8][TOPK];
    const int tid = threadIdx.x, w = tid >> 5, lane = tid & 31;
    const int t = blockIdx.x * 8 + w;
    const float inv_sqrt_r = 0.14433756729740643f;

    float v[32];
    const float* srow = g_scores + (size_t)t * NSLOT;
    #pragma unroll
    for (int i = 0; i < 32; i++)
        v[i] = srow[i * 32 + lane] * inv_sqrt_r + __ldg(&log_rel[i * 32 + lane]);

    for (int sel = 0; sel < TOPK; sel++) {
        float m = -INFINITY; int mi = NSLOT;
        #pragma unroll
        for (int i = 0; i < 32; i++)
            if (v[i] > m) { m = v[i]; mi = i * 32 + lane; }
        #pragma unroll
        for (int off = 16; off >= 1; off >>= 1) {
            float om = __shfl_xor_sync(0xffffffffu, m, off);
            int   omi = __shfl_xor_sync(0xffffffffu, mi, off);
            if (om > m || (om == m && omi < mi)) { m = om; mi = omi; }
        }
        if ((mi & 31) == lane) v[mi >> 5] = -INFINITY;
        if (lane == 0) s_idx[w][sel] = mi;
    }
    __syncwarp();

    if (lane < TOPK) {
        int idx = s_idx[w][lane];
        const float* qr = &g_Q[(size_t)t * BOT];
        const float* kr = &aux_keys[(size_t)idx * BOT];
        float dot = 0.0f;
        #pragma unroll
        for (int c = 0; c < BOT; c++) dot += qr[c] * kr[c];
        float a = dot * 0.125f + log_rel[idx];
        float mx = a;
        #pragma unroll
        for (int off = 4; off >= 1; off >>= 1)
            mx = fmaxf(mx, __shfl_xor_sync(0xffu, mx, off, 8));
        float e = expf(a - mx);
        float se = e;
        #pragma unroll
        for (int off = 4; off >= 1; off >>= 1)
            se += __shfl_xor_sync(0xffu, se, off, 8);
        s_w[w][lane] = e / se;
    }
    __syncwarp();

    int   idxs[TOPK]; float ws[TOPK];
    #pragma unroll
    for (int k = 0; k < TOPK; k++) { idxs[k] = s_idx[w][k]; ws[k] = s_w[w][k]; }
    #pragma unroll
    for (int j = 0; j < VB / 32; j++) {
        int col = lane + j * 32;
        float acc = 0.0f;
        #pragma unroll
        for (int k = 0; k < TOPK; k++)
            acc += ws[k] * g_auxdown[(size_t)idxs[k] * VB + col];
        g_downb[(size_t)t * VB + col] = __float2bfloat16(acc);
    }
}

// ---------------- launch ----------------
extern "C" void kernel_launch(void* const* d_in, const int* in_sizes, int n_in,
                              void* d_out, int out_size) {
    const float* hs       = (const float*)d_in[0];
    const float* Wq       = (const float*)d_in[1];
    const float* Wr       = (const float*)d_in[2];
    const float* aux_keys = (const float*)d_in[3];
    const float* aux_vals = (const float*)d_in[4];
    const float* Wvd      = (const float*)d_in[5];
    const float* Wvu      = (const float*)d_in[6];
    const float* Wu1      = (const float*)d_in[7];
    const float* bu1      = (const float*)d_in[8];
    const float* Wu2      = (const float*)d_in[9];
    const float* bu2      = (const float*)d_in[10];
    const float* gw1      = (const float*)d_in[11];
    const float* gb       = (const float*)d_in[12];
    const float* log_rel  = (const float*)d_in[13];
    float* out = (float*)d_out;

    const int T = in_sizes[0] / HID;   // 4096

    bf16 *pHb, *pWu1b, *pWqb, *pAvalb, *pWvdb, *pWvub, *pQb, *pMslotb, *pDownb;
    float *pQpart, *pRk, *pScores, *pADpart, *pLpart, *pGate;
    cudaGetSymbolAddress((void**)&pHb, g_Hb);
    cudaGetSymbolAddress((void**)&pWu1b, g_Wu1b);
    cudaGetSymbolAddress((void**)&pWqb, g_Wqb);
    cudaGetSymbolAddress((void**)&pAvalb, g_Avalb);
    cudaGetSymbolAddress((void**)&pWvdb, g_Wvdb);
    cudaGetSymbolAddress((void**)&pWvub, g_Wvub);
    cudaGetSymbolAddress((void**)&pQb, g_Qb);
    cudaGetSymbolAddress((void**)&pMslotb, g_Mslotb);
    cudaGetSymbolAddress((void**)&pDownb, g_downb);
    cudaGetSymbolAddress((void**)&pQpart, g_Qpart);
    cudaGetSymbolAddress((void**)&pRk, g_rk);
    cudaGetSymbolAddress((void**)&pScores, g_scores);
    cudaGetSymbolAddress((void**)&pADpart, g_ADpart);
    cudaGetSymbolAddress((void**)&pLpart, g_lpart);
    cudaGetSymbolAddress((void**)&pGate, g_gate);

    // dynamic smem opt-in (idempotent)
    const int SM128 = 2 * (128 + 128) * 72 * 2;   // 73728
    const int SM64  = 2 * (128 + 64) * 72 * 2;    // 55296
    cudaFuncSetAttribute(mma_pipe<128, 0>, cudaFuncAttributeMaxDynamicSharedMemorySize, SM128);
    cudaFuncSetAttribute(mma_pipe<128, 1>, cudaFuncAttributeMaxDynamicSharedMemorySize, SM128);
    cudaFuncSetAttribute(mma_pipe<128, 2>, cudaFuncAttributeMaxDynamicSharedMemorySize, SM128);
    cudaFuncSetAttribute(mma_pipe<64, 0>,  cudaFuncAttributeMaxDynamicSharedMemorySize, SM64);

    // weight conversions
    k_cvt4<<<(HU * HID / 16 + 255) / 256, 256>>>(Wu1, pWu1b, HU * HID / 4);
    k_cvt4<<<(BOT * HID / 16 + 255) / 256, 256>>>(Wq, pWqb, BOT * HID / 4);
    k_cvt4<<<(NSLOT * HID / 16 + 255) / 256, 256>>>(aux_vals, pAvalb, NSLOT * HID / 4);
    k_cvt4<<<(VB * HID / 16 + 255) / 256, 256>>>(Wvd, pWvdb, VB * HID / 4);
    k_cvt4<<<(HID * VB / 16 + 255) / 256, 256>>>(Wvu, pWvub, HID * VB / 4);

    // H -> bf16 + per-token log1p(var); global mean
    k_prep_h<<<T, 256>>>(hs);
    k_mean<<<1, 256>>>(T);

    // Y GEMM fused with learned-reduction: lpart[T][8]
    mma_pipe<128, 2><<<dim3(HU / 128, T / 128, 1), 256, SM128>>>(
        pHb, pWu1b, pLpart, T, HU, HID, bu1, Wu2);
    k_gate<<<T / 256, 256>>>(bu2, gw1, gb);

    // Q = H @ Wq^T  split-K 4 + reduce (fp32 + bf16 copies)
    mma_pipe<64, 0><<<dim3(1, T / 128, 4), 256, SM64>>>(
        pHb, pWqb, pQpart, T, BOT, HID, nullptr, nullptr);
    k_reduceQ<<<(T * BOT / 4 + 255) / 256, 256>>>(T);

    // rk = aux_keys @ Wr^T (SIMT), Mslot = rk @ Wr -> bf16
    gemm_nt<64, 64, 16, 4, 4><<<dim3(1, NSLOT / 64), 256>>>(aux_keys, Wr, pRk, NSLOT, RDIM, BOT);
    k_mslot<<<NSLOT * BOT / 256, 256>>>(Wr);

    // scores = Q @ Mslot^T  [T x 1024], K=64
    mma_pipe<128, 0><<<dim3(NSLOT / 128, T / 128, 1), 256, SM128>>>(
        pQb, pMslotb, pScores, T, NSLOT, BOT, nullptr, nullptr);

    // aux_down = aux_values @ Wvd^T  split-K 8 + reduce
    mma_pipe<128, 0><<<dim3(VB / 128, NSLOT / 128, 8), 256, SM128>>>(
        pAvalb, pWvdb, pADpart, NSLOT, VB, HID, nullptr, nullptr);
    k_reduceAD<<<(NSLOT * VB / 4 + 255) / 256, 256>>>();

    // top-8 + attention + gather -> g_downb
    k_topk<<<T / 8, 256>>>(aux_keys, log_rel);

    // out = hs + gate * (down @ Wvu^T)
    mma_pipe<128, 1><<<dim3(HID / 128, T / 128, 1), 256, SM128>>>(
        pDownb, pWvub, out, T, HID, VB, hs, pGate);
}

// round 6
// speedup vs baseline: 1.3098x; 1.0598x over previous
#include <cuda_runtime.h>
#include <cuda_bf16.h>
#include <math.h>
#include <stdint.h>

#define HID   4096
#define BOT   64
#define RDIM  48
#define NSLOT 1024
#define TOPK  8
#define VB    256
#define HU    1024
#define TMAX  4096

typedef __nv_bfloat16 bf16;

// ---------------- static scratch ----------------
__device__ bf16  g_Hb[(size_t)TMAX * HID];        // 32 MB
__device__ bf16  g_Wu1b[HU * HID];                // 8 MB
__device__ bf16  g_Wqb[BOT * HID];
__device__ bf16  g_Avalb[NSLOT * HID];            // 8 MB
__device__ bf16  g_Wvdb[VB * HID];
__device__ bf16  g_Wvub[HID * VB];
__device__ float g_Qpart[4][TMAX * BOT];          // 4 MB
__device__ float g_Q[TMAX * BOT];
__device__ bf16  g_Qb[TMAX * BOT];
__device__ float g_rk[NSLOT * RDIM];
__device__ bf16  g_Mslotb[NSLOT * BOT];
__device__ float g_scores[(size_t)TMAX * NSLOT];  // 16 MB
__device__ float g_ADpart[8][NSLOT * VB];         // 8 MB
__device__ float g_auxdown[NSLOT * VB];
__device__ bf16  g_downb[TMAX * VB];
__device__ float g_lpart[TMAX * 8];               // Y-epilogue partial sums
__device__ float g_logvar[TMAX];
__device__ float g_gate[TMAX];
__device__ float g_mean[1];

__device__ __forceinline__ float gelu_tanh(float x) {
    float x3 = x * x * x;
    return 0.5f * x * (1.0f + tanhf(0.7978845608028654f * (x + 0.044715f * x3)));
}
__device__ __forceinline__ float sigmoidf(float x) { return 1.0f / (1.0f + expf(-x)); }

// ---------------- ldmatrix / mma / cp.async helpers ----------------
__device__ __forceinline__ uint32_t smem_u32(const void* p) {
    return (uint32_t)__cvta_generic_to_shared(p);
}
__device__ __forceinline__ void ldsm_x4(uint32_t& r0, uint32_t& r1, uint32_t& r2, uint32_t& r3,
                                        const bf16* p) {
    asm volatile("ldmatrix.sync.aligned.m8n8.x4.shared.b16 {%0,%1,%2,%3}, [%4];"
                 : "=r"(r0), "=r"(r1), "=r"(r2), "=r"(r3) : "r"(smem_u32(p)));
}
__device__ __forceinline__ void mma_bf16(float* c, const uint32_t* a, const uint32_t* b) {
    asm volatile(
        "mma.sync.aligned.m16n8k16.row.col.f32.bf16.bf16.f32 "
        "{%0,%1,%2,%3}, {%4,%5,%6,%7}, {%8,%9}, {%0,%1,%2,%3};"
        : "+f"(c[0]), "+f"(c[1]), "+f"(c[2]), "+f"(c[3])
        : "r"(a[0]), "r"(a[1]), "r"(a[2]), "r"(a[3]), "r"(b[0]), "r"(b[1]));
}
__device__ __forceinline__ void cp16(void* s, const void* g) {
    asm volatile("cp.async.cg.shared.global [%0], [%1], 16;"
                 :: "r"(smem_u32(s)), "l"(g));
}
__device__ __forceinline__ void cp_commit() { asm volatile("cp.async.commit_group;"); }
template<int N> __device__ __forceinline__ void cp_wait() {
    asm volatile("cp.async.wait_group %0;" :: "n"(N));
}

// ---------------- pipelined tensor-core GEMM: C[M,N] = A[M,K] @ B[N,K]^T ----------
// BM=128, BK=64, 2-stage cp.async double buffer, 256 threads (warps 4m x 2n).
// __launch_bounds__(256,2) to force 2 CTAs/SM (reg cap 128).
// gridDim.z = deterministic split-K (partials at C + z*M*N).
// EPI 0: fp32 store. EPI 1: C = aux0(hs) + aux1(gate)[row]*acc.
// EPI 2: fused gelu(acc+bu1)*wu2 row-reduction -> C[M][gridDim.x] partials.
template<int BN, int EPI>
__global__ void __launch_bounds__(256, 2)
mma_pipe(const bf16* __restrict__ A, const bf16* __restrict__ B,
         float* __restrict__ C, int M, int N, int K,
         const float* __restrict__ aux0, const float* __restrict__ aux1) {
    constexpr int BM = 128, BK = 64, LDA = 72;       // 144B rows
    constexpr int WN = BN / 2, NT = WN / 8, NP = NT / 2;
    constexpr int ACH = BM * BK / 8;
    constexpr int BCH = BN * BK / 8;
    extern __shared__ bf16 sm[];
    bf16* As = sm;
    bf16* Bs = sm + 2 * BM * LDA;

    __shared__ float s_row[BM][2];
    __shared__ float s_bu1[BN];
    __shared__ float s_wu2[BN];

    const int tid = threadIdx.x, lane = tid & 31, w = tid >> 5;
    const int wm = w & 3, wn = w >> 2;
    const int m0 = blockIdx.y * BM, n0 = blockIdx.x * BN;
    const int kpart = K / gridDim.z;
    const int kbeg = blockIdx.z * kpart;
    const int ntiles = kpart / BK;
    float* Cout = C + (size_t)blockIdx.z * M * N;

    if (EPI == 2) {
        for (int i = tid; i < BN; i += 256) {
            s_bu1[i] = aux0[n0 + i];
            s_wu2[i] = aux1[n0 + i];
        }
    }

    const int lrow = lane & 15;
    const int lco  = (lane >> 4) << 3;

    float acc[2][NT][4];
    #pragma unroll
    for (int i = 0; i < 2; i++)
        #pragma unroll
        for (int j = 0; j < NT; j++)
            #pragma unroll
            for (int q = 0; q < 4; q++) acc[i][j][q] = 0.0f;

    // ---- issue stage 0 ----
    {
        const int kk = kbeg;
        #pragma unroll
        for (int i = tid; i < ACH; i += 256) {
            int r = i >> 3, off = (i & 7) * 8;
            cp16(&As[r * LDA + off], A + (size_t)(m0 + r) * K + kk + off);
        }
        #pragma unroll
        for (int i = tid; i < BCH; i += 256) {
            int r = i >> 3, off = (i & 7) * 8;
            cp16(&Bs[r * LDA + off], B + (size_t)(n0 + r) * K + kk + off);
        }
        cp_commit();
    }

    for (int kt = 0; kt < ntiles; kt++) {
        if (kt + 1 < ntiles) {
            const int st = (kt + 1) & 1;
            const int kk = kbeg + (kt + 1) * BK;
            bf16* Ad = As + st * BM * LDA;
            bf16* Bd = Bs + st * BN * LDA;
            #pragma unroll
            for (int i = tid; i < ACH; i += 256) {
                int r = i >> 3, off = (i & 7) * 8;
                cp16(&Ad[r * LDA + off], A + (size_t)(m0 + r) * K + kk + off);
            }
            #pragma unroll
            for (int i = tid; i < BCH; i += 256) {
                int r = i >> 3, off = (i & 7) * 8;
                cp16(&Bd[r * LDA + off], B + (size_t)(n0 + r) * K + kk + off);
            }
            cp_commit();
            cp_wait<1>();
        } else {
            cp_wait<0>();
        }
        __syncthreads();

        const bf16* Ac = As + (kt & 1) * BM * LDA;
        const bf16* Bc = Bs + (kt & 1) * BN * LDA;
        #pragma unroll
        for (int ks = 0; ks < 4; ks++) {
            uint32_t a[2][4];
            #pragma unroll
            for (int mt = 0; mt < 2; mt++)
                ldsm_x4(a[mt][0], a[mt][1], a[mt][2], a[mt][3],
                        &Ac[(wm * 32 + mt * 16 + lrow) * LDA + ks * 16 + lco]);
            uint32_t bb[NT][2];
            #pragma unroll
            for (int p = 0; p < NP; p++) {
                uint32_t r0, r1, r2, r3;
                ldsm_x4(r0, r1, r2, r3,
                        &Bc[(wn * WN + p * 16 + lrow) * LDA + ks * 16 + lco]);
                bb[2 * p][0] = r0; bb[2 * p][1] = r2;
                bb[2 * p + 1][0] = r1; bb[2 * p + 1][1] = r3;
            }
            #pragma unroll
            for (int mt = 0; mt < 2; mt++)
                #pragma unroll
                for (int nt = 0; nt < NT; nt++)
                    mma_bf16(acc[mt][nt], a[mt], bb[nt]);
        }
        __syncthreads();
    }

    if (EPI == 2) {
        float rs[2][2];
        rs[0][0] = rs[0][1] = rs[1][0] = rs[1][1] = 0.0f;
        #pragma unroll
        for (int mt = 0; mt < 2; mt++) {
            #pragma unroll
            for (int nt = 0; nt < NT; nt++) {
                int lc = wn * WN + nt * 8 + (lane & 3) * 2;
                float b0 = s_bu1[lc], b1 = s_bu1[lc + 1];
                float w0 = s_wu2[lc], w1 = s_wu2[lc + 1];
                rs[mt][0] += gelu_tanh(acc[mt][nt][0] + b0) * w0
                           + gelu_tanh(acc[mt][nt][1] + b1) * w1;
                rs[mt][1] += gelu_tanh(acc[mt][nt][2] + b0) * w0
                           + gelu_tanh(acc[mt][nt][3] + b1) * w1;
            }
        }
        #pragma unroll
        for (int mt = 0; mt < 2; mt++)
            #pragma unroll
            for (int h = 0; h < 2; h++) {
                rs[mt][h] += __shfl_xor_sync(0xffffffffu, rs[mt][h], 1);
                rs[mt][h] += __shfl_xor_sync(0xffffffffu, rs[mt][h], 2);
            }
        if ((lane & 3) == 0) {
            #pragma unroll
            for (int mt = 0; mt < 2; mt++)
                #pragma unroll
                for (int h = 0; h < 2; h++)
                    s_row[wm * 32 + mt * 16 + (lane >> 2) + h * 8][wn] = rs[mt][h];
        }
        __syncthreads();
        if (tid < BM)
            Cout[(size_t)(m0 + tid) * gridDim.x + blockIdx.x] =
                s_row[tid][0] + s_row[tid][1];
        return;
    }

    #pragma unroll
    for (int mt = 0; mt < 2; mt++) {
        int r0 = m0 + wm * 32 + mt * 16 + (lane >> 2);
        float g0 = 0.0f, g1 = 0.0f;
        if (EPI == 1) { g0 = aux1[r0]; g1 = aux1[r0 + 8]; }
        #pragma unroll
        for (int nt = 0; nt < NT; nt++) {
            int cc = n0 + wn * WN + nt * 8 + (lane & 3) * 2;
            size_t o0 = (size_t)r0 * N + cc;
            size_t o1 = (size_t)(r0 + 8) * N + cc;
            if (EPI == 0) {
                Cout[o0]     = acc[mt][nt][0];
                Cout[o0 + 1] = acc[mt][nt][1];
                Cout[o1]     = acc[mt][nt][2];
                Cout[o1 + 1] = acc[mt][nt][3];
            } else {
                Cout[o0]     = aux0[o0]     + g0 * acc[mt][nt][0];
                Cout[o0 + 1] = aux0[o0 + 1] + g0 * acc[mt][nt][1];
                Cout[o1]     = aux0[o1]     + g1 * acc[mt][nt][2];
                Cout[o1 + 1] = aux0[o1 + 1] + g1 * acc[mt][nt][3];
            }
        }
    }
}

// ---------------- SIMT GEMM for tiny rk op ----------------
template<int BM, int BN, int BK, int TM, int TN>
__global__ void gemm_nt(const float* __restrict__ A, const float* __restrict__ B,
                        float* __restrict__ C, int M, int N, int Kd) {
    __shared__ float As[BK][BM + 4];
    __shared__ float Bs[BK][BN + 4];
    constexpr int TX = BN / TN, TY = BM / TM, NTHR = TX * TY;
    const int tid = threadIdx.x;
    const int tx = tid % TX, ty = tid / TX;
    const int m0 = blockIdx.y * BM, n0 = blockIdx.x * BN;
    float acc[TM][TN];
    #pragma unroll
    for (int i = 0; i < TM; i++)
        #pragma unroll
        for (int j = 0; j < TN; j++) acc[i][j] = 0.0f;
    for (int k0 = 0; k0 < Kd; k0 += BK) {
        for (int e = tid; e < BM * BK; e += NTHR) {
            int r = e / BK, c = e % BK;
            As[c][r] = (m0 + r < M) ? A[(size_t)(m0 + r) * Kd + k0 + c] : 0.0f;
        }
        for (int e = tid; e < BN * BK; e += NTHR) {
            int r = e / BK, c = e % BK;
            Bs[c][r] = (n0 + r < N) ? B[(size_t)(n0 + r) * Kd + k0 + c] : 0.0f;
        }
        __syncthreads();
        #pragma unroll
        for (int kk = 0; kk < BK; kk++) {
            float a[TM], b[TN];
            #pragma unroll
            for (int i = 0; i < TM; i++) a[i] = As[kk][ty * TM + i];
            #pragma unroll
            for (int j = 0; j < TN; j++) b[j] = Bs[kk][tx * TN + j];
            #pragma unroll
            for (int i = 0; i < TM; i++)
                #pragma unroll
                for (int j = 0; j < TN; j++) acc[i][j] += a[i] * b[j];
        }
        __syncthreads();
    }
    #pragma unroll
    for (int i = 0; i < TM; i++) {
        int gm = m0 + ty * TM + i;
        if (gm >= M) continue;
        #pragma unroll
        for (int j = 0; j < TN; j++) {
            int gn = n0 + tx * TN + j;
            if (gn < N) C[(size_t)gm * N + gn] = acc[i][j];
        }
    }
}

// ---------------- merged fp32 -> bf16 weight conversion ----------------
__device__ __forceinline__ void cvt1(const float* in, bf16* out, size_t i) {
    float4 f = ((const float4*)in)[i];
    ((__nv_bfloat162*)out)[2 * i]     = __floats2bfloat162_rn(f.x, f.y);
    ((__nv_bfloat162*)out)[2 * i + 1] = __floats2bfloat162_rn(f.z, f.w);
}
// segment sizes in float4: Wu1 1048576 | Wq 65536 | aux 1048576 | Wvd 262144 | Wvu 262144
__global__ void k_cvt_all(const float* w1, const float* w2, const float* w3,
                          const float* w4, const float* w5,
                          bf16* o1, bf16* o2, bf16* o3, bf16* o4, bf16* o5) {
    size_t base = (size_t)(blockIdx.x * 256 + threadIdx.x) * 2;
    #pragma unroll
    for (int j = 0; j < 2; j++) {
        size_t i = base + j;
        if (i < 1048576)            cvt1(w1, o1, i);
        else if (i < 1114112)       cvt1(w2, o2, i - 1048576);
        else if (i < 2162688)       cvt1(w3, o3, i - 1114112);
        else if (i < 2424832)       cvt1(w4, o4, i - 2162688);
        else if (i < 2686976)       cvt1(w5, o5, i - 2424832);
    }
}

// ---------------- fused: hs -> bf16 + per-token log1p(var) ----------------
__global__ void k_prep_h(const float* __restrict__ hs) {
    __shared__ float sh1[256], sh2[256];
    const int t = blockIdx.x, tid = threadIdx.x;
    const float4* row = (const float4*)(hs + (size_t)t * HID);
    __nv_bfloat162* orow = (__nv_bfloat162*)(g_Hb + (size_t)t * HID);
    float s = 0.0f, s2 = 0.0f;
    float4 f[4];
    #pragma unroll
    for (int i = 0; i < 4; i++) f[i] = row[tid + i * 256];
    #pragma unroll
    for (int i = 0; i < 4; i++) {
        int c = tid + i * 256;
        s += f[i].x + f[i].y + f[i].z + f[i].w;
        s2 += f[i].x * f[i].x + f[i].y * f[i].y + f[i].z * f[i].z + f[i].w * f[i].w;
        orow[2 * c]     = __floats2bfloat162_rn(f[i].x, f[i].y);
        orow[2 * c + 1] = __floats2bfloat162_rn(f[i].z, f[i].w);
    }
    sh1[tid] = s; sh2[tid] = s2;
    __syncthreads();
    for (int off = 128; off > 0; off >>= 1) {
        if (tid < off) { sh1[tid] += sh1[tid + off]; sh2[tid] += sh2[tid + off]; }
        __syncthreads();
    }
    if (tid == 0) {
        float mean = sh1[0] * (1.0f / HID);
        float var  = sh2[0] * (1.0f / HID) - mean * mean;
        g_logvar[t] = log1pf(var);
    }
}

__global__ void k_mean(int T) {
    __shared__ float sh[256];
    float s = 0.0f;
    for (int i = threadIdx.x; i < T; i += 256) s += g_logvar[i];
    sh[threadIdx.x] = s;
    __syncthreads();
    for (int off = 128; off > 0; off >>= 1) {
        if (threadIdx.x < off) sh[threadIdx.x] += sh[threadIdx.x + off];
        __syncthreads();
    }
    if (threadIdx.x == 0) g_mean[0] = sh[0] / (float)T;
}

// ---------------- gate from lpart + variance ----------------
__global__ void k_gate(const float* __restrict__ bu2, const float* __restrict__ gw1,
                       const float* __restrict__ gb, int T) {
    int t = blockIdx.x * 256 + threadIdx.x;
    if (t >= T) return;
    float s = 0.0f;
    #pragma unroll
    for (int i = 0; i < 8; i++) s += g_lpart[t * 8 + i];
    float learned = s + bu2[0];
    float nv = g_logvar[t] / (g_mean[0] + 1e-6f);
    float u = fminf(fmaxf(nv * 0.5f + sigmoidf(learned) * 2.5f, 0.0f), 5.0f);
    float un = fminf(fmaxf((u - 0.5f) * (1.0f / 1.5f), 0.0f), 1.0f);
    float g = sigmoidf(gw1[0] * un + gb[0]);
    g_gate[t] = (g < 0.05f) ? 0.0f : g;
}

// ---------------- split-K reductions ----------------
__global__ void k_reduceQ(int T) {
    int i = blockIdx.x * 256 + threadIdx.x;
    if (i >= T * BOT / 4) return;
    float4 a = ((const float4*)g_Qpart[0])[i];
    float4 b = ((const float4*)g_Qpart[1])[i];
    float4 c = ((const float4*)g_Qpart[2])[i];
    float4 d = ((const float4*)g_Qpart[3])[i];
    float4 r; r.x = a.x + b.x + c.x + d.x; r.y = a.y + b.y + c.y + d.y;
    r.z = a.z + b.z + c.z + d.z; r.w = a.w + b.w + c.w + d.w;
    ((float4*)g_Q)[i] = r;
    ((__nv_bfloat162*)g_Qb)[2 * i]     = __floats2bfloat162_rn(r.x, r.y);
    ((__nv_bfloat162*)g_Qb)[2 * i + 1] = __floats2bfloat162_rn(r.z, r.w);
}

__global__ void k_reduceAD() {
    int i = blockIdx.x * 256 + threadIdx.x;
    if (i >= NSLOT * VB / 4) return;
    float4 r = ((const float4*)g_ADpart[0])[i];
    #pragma unroll
    for (int z = 1; z < 8; z++) {
        float4 p = ((const float4*)g_ADpart[z])[i];
        r.x += p.x; r.y += p.y; r.z += p.z; r.w += p.w;
    }
    ((float4*)g_auxdown)[i] = r;
}

// ---------------- Mslot = rk @ Wr -> bf16 ----------------
__global__ void k_mslot(const float* __restrict__ Wr) {
    int idx = blockIdx.x * 256 + threadIdx.x;
    int n = idx >> 6, c = idx & 63;
    float s = 0.0f;
    #pragma unroll
    for (int r = 0; r < RDIM; r++) s += g_rk[n * RDIM + r] * Wr[r * BOT + c];
    g_Mslotb[idx] = __float2bfloat16(s);
}

// ---------------- top-k + attention + bottleneck gather ----------------
__global__ void k_topk(const float* __restrict__ aux_keys,
                       const float* __restrict__ log_rel) {
    __shared__ float s_w[8][TOPK];
    __shared__ int   s_idx[8][TOPK];
    const int tid = threadIdx.x, w = tid >> 5, lane = tid & 31;
    const int t = blockIdx.x * 8 + w;
    const float inv_sqrt_r = 0.14433756729740643f;

    float v[32];
    const float* srow = g_scores + (size_t)t * NSLOT;
    #pragma unroll
    for (int i = 0; i < 32; i++)
        v[i] = srow[i * 32 + lane] * inv_sqrt_r + __ldg(&log_rel[i * 32 + lane]);

    for (int sel = 0; sel < TOPK; sel++) {
        float m = -INFINITY; int mi = NSLOT;
        #pragma unroll
        for (int i = 0; i < 32; i++)
            if (v[i] > m) { m = v[i]; mi = i * 32 + lane; }
        #pragma unroll
        for (int off = 16; off >= 1; off >>= 1) {
            float om = __shfl_xor_sync(0xffffffffu, m, off);
            int   omi = __shfl_xor_sync(0xffffffffu, mi, off);
            if (om > m || (om == m && omi < mi)) { m = om; mi = omi; }
        }
        if ((mi & 31) == lane) v[mi >> 5] = -INFINITY;
        if (lane == 0) s_idx[w][sel] = mi;
    }
    __syncwarp();

    if (lane < TOPK) {
        int idx = s_idx[w][lane];
        const float* qr = &g_Q[(size_t)t * BOT];
        const float* kr = &aux_keys[(size_t)idx * BOT];
        float dot = 0.0f;
        #pragma unroll
        for (int c = 0; c < BOT; c++) dot += qr[c] * kr[c];
        float a = dot * 0.125f + log_rel[idx];
        float mx = a;
        #pragma unroll
        for (int off = 4; off >= 1; off >>= 1)
            mx = fmaxf(mx, __shfl_xor_sync(0xffu, mx, off, 8));
        float e = expf(a - mx);
        float se = e;
        #pragma unroll
        for (int off = 4; off >= 1; off >>= 1)
            se += __shfl_xor_sync(0xffu, se, off, 8);
        s_w[w][lane] = e / se;
    }
    __syncwarp();

    int   idxs[TOPK]; float ws[TOPK];
    #pragma unroll
    for (int k = 0; k < TOPK; k++) { idxs[k] = s_idx[w][k]; ws[k] = s_w[w][k]; }
    #pragma unroll
    for (int j = 0; j < VB / 32; j++) {
        int col = lane + j * 32;
        float acc = 0.0f;
        #pragma unroll
        for (int k = 0; k < TOPK; k++)
            acc += ws[k] * g_auxdown[(size_t)idxs[k] * VB + col];
        g_downb[(size_t)t * VB + col] = __float2bfloat16(acc);
    }
}

// ---------------- launch ----------------
extern "C" void kernel_launch(void* const* d_in, const int* in_sizes, int n_in,
                              void* d_out, int out_size) {
    const float* hs       = (const float*)d_in[0];
    const float* Wq       = (const float*)d_in[1];
    const float* Wr       = (const float*)d_in[2];
    const float* aux_keys = (const float*)d_in[3];
    const float* aux_vals = (const float*)d_in[4];
    const float* Wvd      = (const float*)d_in[5];
    const float* Wvu      = (const float*)d_in[6];
    const float* Wu1      = (const float*)d_in[7];
    const float* bu1      = (const float*)d_in[8];
    const float* Wu2      = (const float*)d_in[9];
    const float* bu2      = (const float*)d_in[10];
    const float* gw1      = (const float*)d_in[11];
    const float* gb       = (const float*)d_in[12];
    const float* log_rel  = (const float*)d_in[13];
    float* out = (float*)d_out;

    const int T = in_sizes[0] / HID;   // 4096

    bf16 *pHb, *pWu1b, *pWqb, *pAvalb, *pWvdb, *pWvub, *pQb, *pMslotb, *pDownb;
    float *pQpart, *pRk, *pScores, *pADpart, *pLpart, *pGate;
    cudaGetSymbolAddress((void**)&pHb, g_Hb);
    cudaGetSymbolAddress((void**)&pWu1b, g_Wu1b);
    cudaGetSymbolAddress((void**)&pWqb, g_Wqb);
    cudaGetSymbolAddress((void**)&pAvalb, g_Avalb);
    cudaGetSymbolAddress((void**)&pWvdb, g_Wvdb);
    cudaGetSymbolAddress((void**)&pWvub, g_Wvub);
    cudaGetSymbolAddress((void**)&pQb, g_Qb);
    cudaGetSymbolAddress((void**)&pMslotb, g_Mslotb);
    cudaGetSymbolAddress((void**)&pDownb, g_downb);
    cudaGetSymbolAddress((void**)&pQpart, g_Qpart);
    cudaGetSymbolAddress((void**)&pRk, g_rk);
    cudaGetSymbolAddress((void**)&pScores, g_scores);
    cudaGetSymbolAddress((void**)&pADpart, g_ADpart);
    cudaGetSymbolAddress((void**)&pLpart, g_lpart);
    cudaGetSymbolAddress((void**)&pGate, g_gate);

    const int SM128 = 2 * (128 + 128) * 72 * 2;   // 73728
    const int SM64  = 2 * (128 + 64) * 72 * 2;    // 55296
    cudaFuncSetAttribute(mma_pipe<128, 0>, cudaFuncAttributeMaxDynamicSharedMemorySize, SM128);
    cudaFuncSetAttribute(mma_pipe<128, 1>, cudaFuncAttributeMaxDynamicSharedMemorySize, SM128);
    cudaFuncSetAttribute(mma_pipe<128, 2>, cudaFuncAttributeMaxDynamicSharedMemorySize, SM128);
    cudaFuncSetAttribute(mma_pipe<64, 0>,  cudaFuncAttributeMaxDynamicSharedMemorySize, SM64);

    // launch 0: merged weight conversions
    k_cvt_all<<<(2686976 / 2 + 255) / 256, 256>>>(Wu1, Wq, aux_vals, Wvd, Wvu,
                                                  pWu1b, pWqb, pAvalb, pWvdb, pWvub);
    // launch 1-2: H -> bf16 + variance; global mean
    k_prep_h<<<T, 256>>>(hs);
    k_mean<<<1, 256>>>(T);
    // launch 3-4: independent small ops (hoisted so launch 5 = Y GEMM for ncu -s 5)
    gemm_nt<64, 64, 16, 4, 4><<<dim3(1, NSLOT / 64), 256>>>(aux_keys, Wr, pRk, NSLOT, RDIM, BOT);
    k_mslot<<<NSLOT * BOT / 256, 256>>>(Wr);

    // launch 5: Y GEMM fused with learned-reduction -> lpart[T][8]   (profiled)
    mma_pipe<128, 2><<<dim3(HU / 128, T / 128, 1), 256, SM128>>>(
        pHb, pWu1b, pLpart, T, HU, HID, bu1, Wu2);
    k_gate<<<(T + 255) / 256, 256>>>(bu2, gw1, gb, T);

    // Q = H @ Wq^T  split-K 4 + reduce
    mma_pipe<64, 0><<<dim3(1, T / 128, 4), 256, SM64>>>(
        pHb, pWqb, pQpart, T, BOT, HID, nullptr, nullptr);
    k_reduceQ<<<(T * BOT / 4 + 255) / 256, 256>>>(T);

    // scores = Q @ Mslot^T  [T x 1024], K=64
    mma_pipe<128, 0><<<dim3(NSLOT / 128, T / 128, 1), 256, SM128>>>(
        pQb, pMslotb, pScores, T, NSLOT, BOT, nullptr, nullptr);

    // aux_down = aux_values @ Wvd^T  split-K 8 + reduce
    mma_pipe<128, 0><<<dim3(VB / 128, NSLOT / 128, 8), 256, SM128>>>(
        pAvalb, pWvdb, pADpart, NSLOT, VB, HID, nullptr, nullptr);
    k_reduceAD<<<(NSLOT * VB / 4 + 255) / 256, 256>>>();

    // top-8 + attention + gather -> g_downb
    k_topk<<<T / 8, 256>>>(aux_keys, log_rel);

    // out = hs + gate * (down @ Wvu^T)
    mma_pipe<128, 1><<<dim3(HID / 128, T / 128, 1), 256, SM128>>>(
        pDownb, pWvub, out, T, HID, VB, hs, pGate);
}

// round 8
// speedup vs baseline: 1.4194x; 1.0837x over previous
#include <cuda_runtime.h>
#include <cuda_bf16.h>
#include <math.h>
#include <stdint.h>

#define HID   4096
#define BOT   64
#define RDIM  48
#define NSLOT 1024
#define TOPK  8
#define VB    256
#define HU    1024
#define TMAX  4096

typedef __nv_bfloat16 bf16;

// ---------------- static scratch ----------------
__device__ bf16  g_Hb[(size_t)TMAX * HID];        // 32 MB
__device__ bf16  g_Wu1b[HU * HID];                // 8 MB
__device__ bf16  g_Wqpadb[128 * HID];             // padded to 128 rows (rows 64..127 zero)
__device__ bf16  g_Avalb[NSLOT * HID];            // 8 MB
__device__ bf16  g_Wvdb[VB * HID];
__device__ bf16  g_Wvub[HID * VB];
__device__ float g_Qpart[4][TMAX * 128];          // 8 MB (padded N)
__device__ float g_Q[TMAX * BOT];
__device__ bf16  g_Qb[TMAX * BOT];
__device__ float g_rk[NSLOT * RDIM];
__device__ bf16  g_Mslotb[NSLOT * BOT];
__device__ float g_scores[(size_t)TMAX * NSLOT];  // 16 MB
__device__ float g_ADpart[8][NSLOT * VB];         // 8 MB
__device__ float g_auxdown[NSLOT * VB];
__device__ bf16  g_downb[TMAX * VB];
__device__ float g_lpart[TMAX * 8];               // Y-epilogue partial sums
__device__ float g_logvar[TMAX];
__device__ float g_gate[TMAX];

__device__ __forceinline__ float gelu_tanh(float x) {
    float x3 = x * x * x;
    return 0.5f * x * (1.0f + tanhf(0.7978845608028654f * (x + 0.044715f * x3)));
}
__device__ __forceinline__ float sigmoidf(float x) { return 1.0f / (1.0f + expf(-x)); }

// ---------------- ldmatrix / mma / cp.async helpers ----------------
__device__ __forceinline__ uint32_t smem_u32(const void* p) {
    return (uint32_t)__cvta_generic_to_shared(p);
}
__device__ __forceinline__ void ldsm_x4(uint32_t& r0, uint32_t& r1, uint32_t& r2, uint32_t& r3,
                                        const bf16* p) {
    asm volatile("ldmatrix.sync.aligned.m8n8.x4.shared.b16 {%0,%1,%2,%3}, [%4];"
                 : "=r"(r0), "=r"(r1), "=r"(r2), "=r"(r3) : "r"(smem_u32(p)));
}
__device__ __forceinline__ void mma_bf16(float* c, const uint32_t* a, const uint32_t* b) {
    asm volatile(
        "mma.sync.aligned.m16n8k16.row.col.f32.bf16.bf16.f32 "
        "{%0,%1,%2,%3}, {%4,%5,%6,%7}, {%8,%9}, {%0,%1,%2,%3};"
        : "+f"(c[0]), "+f"(c[1]), "+f"(c[2]), "+f"(c[3])
        : "r"(a[0]), "r"(a[1]), "r"(a[2]), "r"(a[3]), "r"(b[0]), "r"(b[1]));
}
__device__ __forceinline__ void cp16(void* s, const void* g) {
    asm volatile("cp.async.cg.shared.global [%0], [%1], 16;"
                 :: "r"(smem_u32(s)), "l"(g));
}
__device__ __forceinline__ void cp_commit() { asm volatile("cp.async.commit_group;"); }
template<int N> __device__ __forceinline__ void cp_wait() {
    asm volatile("cp.async.wait_group %0;" :: "n"(N));
}

// =====================================================================
// MEGA GEMM: Y (EPI2) + Q padded (split-K 4) + aux_down (split-K 8)
// in one launch; 1D grid, range dispatch. BM=128, BN=128, BK=64.
// =====================================================================
__global__ void __launch_bounds__(256, 2)
mma_mega(const bf16* __restrict__ Hb, const bf16* __restrict__ Wu1b,
         float* __restrict__ lpart,
         const bf16* __restrict__ Wqpadb, float* __restrict__ Qpart,
         const bf16* __restrict__ Avalb, const bf16* __restrict__ Wvdb,
         float* __restrict__ ADpart,
         const float* __restrict__ bu1, const float* __restrict__ wu2, int T) {
    constexpr int BM = 128, BN = 128, BK = 64, LDA = 72;
    constexpr int WN = BN / 2, NT = WN / 8, NP = NT / 2;
    constexpr int ACH = BM * BK / 8, BCH = BN * BK / 8;
    extern __shared__ bf16 sm[];
    bf16* As = sm;
    bf16* Bs = sm + 2 * BM * LDA;

    __shared__ float s_row[BM][2];
    __shared__ float s_bu1[BN];
    __shared__ float s_wu2[BN];

    const int tid = threadIdx.x, lane = tid & 31, w = tid >> 5;
    const int wm = w & 3, wn = w >> 2;
    const int bid = blockIdx.x;

    const bf16 *A, *B;
    float* Cout;
    int N, K, m0, n0, kbeg, kpart, epi, bxs = 0;
    if (bid < 256) {                       // Y: [T x 1024], K=4096, EPI2
        int bx = bid & 7, by = bid >> 3;
        A = Hb; B = Wu1b; Cout = lpart;
        N = HU; K = HID; kbeg = 0; kpart = HID; epi = 2;
        m0 = by * BM; n0 = bx * BN; bxs = bx;
    } else if (bid < 384) {                // Q: [T x 128pad], split-K 4
        int i = bid - 256, z = i >> 5, by = i & 31;
        A = Hb; B = Wqpadb; Cout = Qpart + (size_t)z * T * 128;
        N = 128; K = HID; kpart = HID / 4; kbeg = z * kpart; epi = 0;
        m0 = by * BM; n0 = 0;
    } else {                               // AD: [1024 x 256], split-K 8
        int i = bid - 384, z = i >> 4, r = i & 15;
        int bx = r & 1, by = r >> 1;
        A = Avalb; B = Wvdb; Cout = ADpart + (size_t)z * NSLOT * VB;
        N = VB; K = HID; kpart = HID / 8; kbeg = z * kpart; epi = 0;
        m0 = by * BM; n0 = bx * BN;
    }
    const int ntiles = kpart / BK;

    if (epi == 2) {
        for (int i = tid; i < BN; i += 256) {
            s_bu1[i] = bu1[n0 + i];
            s_wu2[i] = wu2[n0 + i];
        }
    }

    const int lrow = lane & 15;
    const int lco  = (lane >> 4) << 3;

    float acc[2][NT][4];
    #pragma unroll
    for (int i = 0; i < 2; i++)
        #pragma unroll
        for (int j = 0; j < NT; j++)
            #pragma unroll
            for (int q = 0; q < 4; q++) acc[i][j][q] = 0.0f;

    // stage 0
    {
        const int kk = kbeg;
        #pragma unroll
        for (int i = tid; i < ACH; i += 256) {
            int r = i >> 3, off = (i & 7) * 8;
            cp16(&As[r * LDA + off], A + (size_t)(m0 + r) * K + kk + off);
        }
        #pragma unroll
        for (int i = tid; i < BCH; i += 256) {
            int r = i >> 3, off = (i & 7) * 8;
            cp16(&Bs[r * LDA + off], B + (size_t)(n0 + r) * K + kk + off);
        }
        cp_commit();
    }

    for (int kt = 0; kt < ntiles; kt++) {
        if (kt + 1 < ntiles) {
            const int st = (kt + 1) & 1;
            const int kk = kbeg + (kt + 1) * BK;
            bf16* Ad = As + st * BM * LDA;
            bf16* Bd = Bs + st * BN * LDA;
            #pragma unroll
            for (int i = tid; i < ACH; i += 256) {
                int r = i >> 3, off = (i & 7) * 8;
                cp16(&Ad[r * LDA + off], A + (size_t)(m0 + r) * K + kk + off);
            }
            #pragma unroll
            for (int i = tid; i < BCH; i += 256) {
                int r = i >> 3, off = (i & 7) * 8;
                cp16(&Bd[r * LDA + off], B + (size_t)(n0 + r) * K + kk + off);
            }
            cp_commit();
            cp_wait<1>();
        } else {
            cp_wait<0>();
        }
        __syncthreads();

        const bf16* Ac = As + (kt & 1) * BM * LDA;
        const bf16* Bc = Bs + (kt & 1) * BN * LDA;
        #pragma unroll
        for (int ks = 0; ks < 4; ks++) {
            uint32_t a[2][4];
            #pragma unroll
            for (int mt = 0; mt < 2; mt++)
                ldsm_x4(a[mt][0], a[mt][1], a[mt][2], a[mt][3],
                        &Ac[(wm * 32 + mt * 16 + lrow) * LDA + ks * 16 + lco]);
            uint32_t bb[NT][2];
            #pragma unroll
            for (int p = 0; p < NP; p++) {
                uint32_t r0, r1, r2, r3;
                ldsm_x4(r0, r1, r2, r3,
                        &Bc[(wn * WN + p * 16 + lrow) * LDA + ks * 16 + lco]);
                bb[2 * p][0] = r0; bb[2 * p][1] = r2;
                bb[2 * p + 1][0] = r1; bb[2 * p + 1][1] = r3;
            }
            #pragma unroll
            for (int mt = 0; mt < 2; mt++)
                #pragma unroll
                for (int nt = 0; nt < NT; nt++)
                    mma_bf16(acc[mt][nt], a[mt], bb[nt]);
        }
        __syncthreads();
    }

    if (epi == 2) {
        float rs[2][2];
        rs[0][0] = rs[0][1] = rs[1][0] = rs[1][1] = 0.0f;
        #pragma unroll
        for (int mt = 0; mt < 2; mt++) {
            #pragma unroll
            for (int nt = 0; nt < NT; nt++) {
                int lc = wn * WN + nt * 8 + (lane & 3) * 2;
                float b0 = s_bu1[lc], b1 = s_bu1[lc + 1];
                float w0 = s_wu2[lc], w1 = s_wu2[lc + 1];
                rs[mt][0] += gelu_tanh(acc[mt][nt][0] + b0) * w0
                           + gelu_tanh(acc[mt][nt][1] + b1) * w1;
                rs[mt][1] += gelu_tanh(acc[mt][nt][2] + b0) * w0
                           + gelu_tanh(acc[mt][nt][3] + b1) * w1;
            }
        }
        #pragma unroll
        for (int mt = 0; mt < 2; mt++)
            #pragma unroll
            for (int h = 0; h < 2; h++) {
                rs[mt][h] += __shfl_xor_sync(0xffffffffu, rs[mt][h], 1);
                rs[mt][h] += __shfl_xor_sync(0xffffffffu, rs[mt][h], 2);
            }
        if ((lane & 3) == 0) {
            #pragma unroll
            for (int mt = 0; mt < 2; mt++)
                #pragma unroll
                for (int h = 0; h < 2; h++)
                    s_row[wm * 32 + mt * 16 + (lane >> 2) + h * 8][wn] = rs[mt][h];
        }
        __syncthreads();
        if (tid < BM)
            Cout[(size_t)(m0 + tid) * 8 + bxs] = s_row[tid][0] + s_row[tid][1];
        return;
    }

    #pragma unroll
    for (int mt = 0; mt < 2; mt++) {
        int r0 = m0 + wm * 32 + mt * 16 + (lane >> 2);
        #pragma unroll
        for (int nt = 0; nt < NT; nt++) {
            int cc = n0 + wn * WN + nt * 8 + (lane & 3) * 2;
            size_t o0 = (size_t)r0 * N + cc;
            size_t o1 = (size_t)(r0 + 8) * N + cc;
            Cout[o0]     = acc[mt][nt][0];
            Cout[o0 + 1] = acc[mt][nt][1];
            Cout[o1]     = acc[mt][nt][2];
            Cout[o1 + 1] = acc[mt][nt][3];
        }
    }
}

// ---------------- standalone GEMM for scores / out ----------------
// EPI 0: fp32 store. EPI 1: C = aux0(hs) + aux1(gate)[row]*acc.
template<int BN, int EPI>
__global__ void __launch_bounds__(256, 2)
mma_pipe(const bf16* __restrict__ A, const bf16* __restrict__ B,
         float* __restrict__ C, int M, int N, int K,
         const float* __restrict__ aux0, const float* __restrict__ aux1) {
    constexpr int BM = 128, BK = 64, LDA = 72;
    constexpr int WN = BN / 2, NT = WN / 8, NP = NT / 2;
    constexpr int ACH = BM * BK / 8, BCH = BN * BK / 8;
    extern __shared__ bf16 sm[];
    bf16* As = sm;
    bf16* Bs = sm + 2 * BM * LDA;

    const int tid = threadIdx.x, lane = tid & 31, w = tid >> 5;
    const int wm = w & 3, wn = w >> 2;
    const int m0 = blockIdx.y * BM, n0 = blockIdx.x * BN;
    const int ntiles = K / BK;

    const int lrow = lane & 15, lco = (lane >> 4) << 3;
    float acc[2][NT][4];
    #pragma unroll
    for (int i = 0; i < 2; i++)
        #pragma unroll
        for (int j = 0; j < NT; j++)
            #pragma unroll
            for (int q = 0; q < 4; q++) acc[i][j][q] = 0.0f;

    {
        #pragma unroll
        for (int i = tid; i < ACH; i += 256) {
            int r = i >> 3, off = (i & 7) * 8;
            cp16(&As[r * LDA + off], A + (size_t)(m0 + r) * K + off);
        }
        #pragma unroll
        for (int i = tid; i < BCH; i += 256) {
            int r = i >> 3, off = (i & 7) * 8;
            cp16(&Bs[r * LDA + off], B + (size_t)(n0 + r) * K + off);
        }
        cp_commit();
    }

    for (int kt = 0; kt < ntiles; kt++) {
        if (kt + 1 < ntiles) {
            const int st = (kt + 1) & 1;
            const int kk = (kt + 1) * BK;
            bf16* Ad = As + st * BM * LDA;
            bf16* Bd = Bs + st * BN * LDA;
            #pragma unroll
            for (int i = tid; i < ACH; i += 256) {
                int r = i >> 3, off = (i & 7) * 8;
                cp16(&Ad[r * LDA + off], A + (size_t)(m0 + r) * K + kk + off);
            }
            #pragma unroll
            for (int i = tid; i < BCH; i += 256) {
                int r = i >> 3, off = (i & 7) * 8;
                cp16(&Bd[r * LDA + off], B + (size_t)(n0 + r) * K + kk + off);
            }
            cp_commit();
            cp_wait<1>();
        } else {
            cp_wait<0>();
        }
        __syncthreads();

        const bf16* Ac = As + (kt & 1) * BM * LDA;
        const bf16* Bc = Bs + (kt & 1) * BN * LDA;
        #pragma unroll
        for (int ks = 0; ks < 4; ks++) {
            uint32_t a[2][4];
            #pragma unroll
            for (int mt = 0; mt < 2; mt++)
                ldsm_x4(a[mt][0], a[mt][1], a[mt][2], a[mt][3],
                        &Ac[(wm * 32 + mt * 16 + lrow) * LDA + ks * 16 + lco]);
            uint32_t bb[NT][2];
            #pragma unroll
            for (int p = 0; p < NP; p++) {
                uint32_t r0, r1, r2, r3;
                ldsm_x4(r0, r1, r2, r3,
                        &Bc[(wn * WN + p * 16 + lrow) * LDA + ks * 16 + lco]);
                bb[2 * p][0] = r0; bb[2 * p][1] = r2;
                bb[2 * p + 1][0] = r1; bb[2 * p + 1][1] = r3;
            }
            #pragma unroll
            for (int mt = 0; mt < 2; mt++)
                #pragma unroll
                for (int nt = 0; nt < NT; nt++)
                    mma_bf16(acc[mt][nt], a[mt], bb[nt]);
        }
        __syncthreads();
    }

    #pragma unroll
    for (int mt = 0; mt < 2; mt++) {
        int r0 = m0 + wm * 32 + mt * 16 + (lane >> 2);
        float g0 = 0.0f, g1 = 0.0f;
        if (EPI == 1) { g0 = aux1[r0]; g1 = aux1[r0 + 8]; }
        #pragma unroll
        for (int nt = 0; nt < NT; nt++) {
            int cc = n0 + wn * WN + nt * 8 + (lane & 3) * 2;
            size_t o0 = (size_t)r0 * N + cc;
            size_t o1 = (size_t)(r0 + 8) * N + cc;
            if (EPI == 0) {
                C[o0]     = acc[mt][nt][0];
                C[o0 + 1] = acc[mt][nt][1];
                C[o1]     = acc[mt][nt][2];
                C[o1 + 1] = acc[mt][nt][3];
            } else {
                C[o0]     = aux0[o0]     + g0 * acc[mt][nt][0];
                C[o0 + 1] = aux0[o0 + 1] + g0 * acc[mt][nt][1];
                C[o1]     = aux0[o1]     + g1 * acc[mt][nt][2];
                C[o1 + 1] = aux0[o1 + 1] + g1 * acc[mt][nt][3];
            }
        }
    }
}

// =====================================================================
// L0: merged weight conversions + Wq pad-zero + rk dots
// =====================================================================
__device__ __forceinline__ void cvt1(const float* in, bf16* out, size_t i) {
    float4 f = ((const float4*)in)[i];
    ((__nv_bfloat162*)out)[2 * i]     = __floats2bfloat162_rn(f.x, f.y);
    ((__nv_bfloat162*)out)[2 * i + 1] = __floats2bfloat162_rn(f.z, f.w);
}
// cvt blocks: 5248 | pad blocks: 64 | rk blocks: 192  -> grid 5504
__global__ void k_cvt_rk(const float* w1, const float* w2, const float* w3,
                         const float* w4, const float* w5,
                         const float* aux_keys, const float* Wr) {
    const int bid = blockIdx.x, tid = threadIdx.x;
    if (bid < 5248) {
        size_t base = (size_t)(bid * 256 + tid) * 2;
        #pragma unroll
        for (int j = 0; j < 2; j++) {
            size_t i = base + j;
            if (i < 1048576)            cvt1(w1, g_Wu1b, i);
            else if (i < 1114112)       cvt1(w2, g_Wqpadb, i - 1048576);
            else if (i < 2162688)       cvt1(w3, g_Avalb, i - 1114112);
            else if (i < 2424832)       cvt1(w4, g_Wvdb, i - 2162688);
            else if (i < 2686976)       cvt1(w5, g_Wvub, i - 2424832);
        }
    } else if (bid < 5312) {
        // zero rows 64..127 of Wqpadb: uint4 units [32768, 65536)
        int u = (bid - 5248) * 256 + tid;
        uint4 z = make_uint4(0, 0, 0, 0);
        ((uint4*)g_Wqpadb)[32768 + 2 * u]     = z;
        ((uint4*)g_Wqpadb)[32768 + 2 * u + 1] = z;
    } else {
        // rk[n][r] = dot64(aux_keys[n], Wr[r])
        int g = (bid - 5312) * 256 + tid;      // [0, 49152)
        int n = g / RDIM, r = g % RDIM;
        const float4* ar = (const float4*)(aux_keys + (size_t)n * BOT);
        const float4* wr = (const float4*)(Wr + (size_t)r * BOT);
        float s = 0.0f;
        #pragma unroll
        for (int i = 0; i < 16; i++) {
            float4 a = ar[i], b = wr[i];
            s += a.x * b.x + a.y * b.y + a.z * b.z + a.w * b.w;
        }
        g_rk[n * RDIM + r] = s;
    }
}

// =====================================================================
// L1: hs -> bf16 + log1p(var) per token (+ mslot blocks)
// =====================================================================
__global__ void k_prep_mslot(const float* __restrict__ hs, const float* __restrict__ Wr,
                             int T) {
    if ((int)blockIdx.x < T) {
        __shared__ float sh1[256], sh2[256];
        const int t = blockIdx.x, tid = threadIdx.x;
        const float4* row = (const float4*)(hs + (size_t)t * HID);
        __nv_bfloat162* orow = (__nv_bfloat162*)(g_Hb + (size_t)t * HID);
        float s = 0.0f, s2 = 0.0f;
        float4 f[4];
        #pragma unroll
        for (int i = 0; i < 4; i++) f[i] = row[tid + i * 256];
        #pragma unroll
        for (int i = 0; i < 4; i++) {
            int c = tid + i * 256;
            s += f[i].x + f[i].y + f[i].z + f[i].w;
            s2 += f[i].x * f[i].x + f[i].y * f[i].y + f[i].z * f[i].z + f[i].w * f[i].w;
            orow[2 * c]     = __floats2bfloat162_rn(f[i].x, f[i].y);
            orow[2 * c + 1] = __floats2bfloat162_rn(f[i].z, f[i].w);
        }
        sh1[tid] = s; sh2[tid] = s2;
        __syncthreads();
        for (int off = 128; off > 0; off >>= 1) {
            if (tid < off) { sh1[tid] += sh1[tid + off]; sh2[tid] += sh2[tid + off]; }
            __syncthreads();
        }
        if (tid == 0) {
            float mean = sh1[0] * (1.0f / HID);
            float var  = sh2[0] * (1.0f / HID) - mean * mean;
            g_logvar[t] = log1pf(var);
        }
    } else {
        // Mslot = rk @ Wr  -> bf16, 65536 elements over 256 blocks
        int idx = (blockIdx.x - T) * 256 + threadIdx.x;
        int n = idx >> 6, c = idx & 63;
        float s = 0.0f;
        #pragma unroll
        for (int r = 0; r < RDIM; r++) s += g_rk[n * RDIM + r] * Wr[r * BOT + c];
        g_Mslotb[idx] = __float2bfloat16(s);
    }
}

// =====================================================================
// L3: reduceQ (256) + reduceAD (256) + gate w/ inline mean (16) -> 528 blocks
// =====================================================================
__global__ void k_post(const float* __restrict__ bu2, const float* __restrict__ gw1,
                       const float* __restrict__ gb, int T) {
    const int bid = blockIdx.x, tid = threadIdx.x;
    if (bid < 256) {
        // reduceQ: i over T*64/4 float4s; Qpart row stride 128 (padded)
        int i = bid * 256 + tid;               // [0, 65536)
        int t = i >> 4, c4 = i & 15;
        size_t off = (size_t)t * 128 + c4 * 4;
        float4 r = *(const float4*)(&g_Qpart[0][off]);
        #pragma unroll
        for (int z = 1; z < 4; z++) {
            float4 p = *(const float4*)(&g_Qpart[z][off]);
            r.x += p.x; r.y += p.y; r.z += p.z; r.w += p.w;
        }
        ((float4*)g_Q)[i] = r;
        ((__nv_bfloat162*)g_Qb)[2 * i]     = __floats2bfloat162_rn(r.x, r.y);
        ((__nv_bfloat162*)g_Qb)[2 * i + 1] = __floats2bfloat162_rn(r.z, r.w);
    } else if (bid < 512) {
        int i = (bid - 256) * 256 + tid;       // [0, 65536)
        float4 r = ((const float4*)g_ADpart[0])[i];
        #pragma unroll
        for (int z = 1; z < 8; z++) {
            float4 p = ((const float4*)g_ADpart[z])[i];
            r.x += p.x; r.y += p.y; r.z += p.z; r.w += p.w;
        }
        ((float4*)g_auxdown)[i] = r;
    } else {
        // gate blocks: inline deterministic mean of logvar, then gate per token
        __shared__ float sh[256];
        __shared__ float s_mean;
        float s = 0.0f;
        for (int i = tid; i < T; i += 256) s += g_logvar[i];
        sh[tid] = s;
        __syncthreads();
        for (int off = 128; off > 0; off >>= 1) {
            if (tid < off) sh[tid] += sh[tid + off];
            __syncthreads();
        }
        if (tid == 0) s_mean = sh[0] / (float)T;
        __syncthreads();
        int t = (bid - 512) * 256 + tid;
        if (t < T) {
            float acc = 0.0f;
            #pragma unroll
            for (int i = 0; i < 8; i++) acc += g_lpart[t * 8 + i];
            float learned = acc + bu2[0];
            float nv = g_logvar[t] / (s_mean + 1e-6f);
            float u = fminf(fmaxf(nv * 0.5f + sigmoidf(learned) * 2.5f, 0.0f), 5.0f);
            float un = fminf(fmaxf((u - 0.5f) * (1.0f / 1.5f), 0.0f), 1.0f);
            float g = sigmoidf(gw1[0] * un + gb[0]);
            g_gate[t] = (g < 0.05f) ? 0.0f : g;
        }
    }
}

// ---------------- top-k + attention + bottleneck gather ----------------
__global__ void k_topk(const float* __restrict__ aux_keys,
                       const float* __restrict__ log_rel) {
    __shared__ float s_w[8][TOPK];
    __shared__ int   s_idx[8][TOPK];
    const int tid = threadIdx.x, w = tid >> 5, lane = tid & 31;
    const int t = blockIdx.x * 8 + w;
    const float inv_sqrt_r = 0.14433756729740643f;

    float v[32];
    const float* srow = g_scores + (size_t)t * NSLOT;
    #pragma unroll
    for (int i = 0; i < 32; i++)
        v[i] = srow[i * 32 + lane] * inv_sqrt_r + __ldg(&log_rel[i * 32 + lane]);

    for (int sel = 0; sel < TOPK; sel++) {
        float m = -INFINITY; int mi = NSLOT;
        #pragma unroll
        for (int i = 0; i < 32; i++)
            if (v[i] > m) { m = v[i]; mi = i * 32 + lane; }
        #pragma unroll
        for (int off = 16; off >= 1; off >>= 1) {
            float om = __shfl_xor_sync(0xffffffffu, m, off);
            int   omi = __shfl_xor_sync(0xffffffffu, mi, off);
            if (om > m || (om == m && omi < mi)) { m = om; mi = omi; }
        }
        if ((mi & 31) == lane) v[mi >> 5] = -INFINITY;
        if (lane == 0) s_idx[w][sel] = mi;
    }
    __syncwarp();

    if (lane < TOPK) {
        int idx = s_idx[w][lane];
        const float* qr = &g_Q[(size_t)t * BOT];
        const float* kr = &aux_keys[(size_t)idx * BOT];
        float dot = 0.0f;
        #pragma unroll
        for (int c = 0; c < BOT; c++) dot += qr[c] * kr[c];
        float a = dot * 0.125f + log_rel[idx];
        float mx = a;
        #pragma unroll
        for (int off = 4; off >= 1; off >>= 1)
            mx = fmaxf(mx, __shfl_xor_sync(0xffu, mx, off, 8));
        float e = expf(a - mx);
        float se = e;
        #pragma unroll
        for (int off = 4; off >= 1; off >>= 1)
            se += __shfl_xor_sync(0xffu, se, off, 8);
        s_w[w][lane] = e / se;
    }
    __syncwarp();

    int   idxs[TOPK]; float ws[TOPK];
    #pragma unroll
    for (int k = 0; k < TOPK; k++) { idxs[k] = s_idx[w][k]; ws[k] = s_w[w][k]; }
    #pragma unroll
    for (int j = 0; j < VB / 32; j++) {
        int col = lane + j * 32;
        float acc = 0.0f;
        #pragma unroll
        for (int k = 0; k < TOPK; k++)
            acc += ws[k] * g_auxdown[(size_t)idxs[k] * VB + col];
        g_downb[(size_t)t * VB + col] = __float2bfloat16(acc);
    }
}

// ---------------- launch ----------------
extern "C" void kernel_launch(void* const* d_in, const int* in_sizes, int n_in,
                              void* d_out, int out_size) {
    const float* hs       = (const float*)d_in[0];
    const float* Wq       = (const float*)d_in[1];
    const float* Wr       = (const float*)d_in[2];
    const float* aux_keys = (const float*)d_in[3];
    const float* aux_vals = (const float*)d_in[4];
    const float* Wvd      = (const float*)d_in[5];
    const float* Wvu      = (const float*)d_in[6];
    const float* Wu1      = (const float*)d_in[7];
    const float* bu1      = (const float*)d_in[8];
    const float* Wu2      = (const float*)d_in[9];
    const float* bu2      = (const float*)d_in[10];
    const float* gw1      = (const float*)d_in[11];
    const float* gb       = (const float*)d_in[12];
    const float* log_rel  = (const float*)d_in[13];
    float* out = (float*)d_out;

    const int T = in_sizes[0] / HID;   // 4096

    bf16 *pHb, *pWu1b, *pWqpadb, *pAvalb, *pWvdb, *pWvub, *pQb, *pMslotb, *pDownb;
    float *pQpart, *pScores, *pADpart, *pLpart, *pGate;
    cudaGetSymbolAddress((void**)&pHb, g_Hb);
    cudaGetSymbolAddress((void**)&pWu1b, g_Wu1b);
    cudaGetSymbolAddress((void**)&pWqpadb, g_Wqpadb);
    cudaGetSymbolAddress((void**)&pAvalb, g_Avalb);
    cudaGetSymbolAddress((void**)&pWvdb, g_Wvdb);
    cudaGetSymbolAddress((void**)&pWvub, g_Wvub);
    cudaGetSymbolAddress((void**)&pQb, g_Qb);
    cudaGetSymbolAddress((void**)&pMslotb, g_Mslotb);
    cudaGetSymbolAddress((void**)&pDownb, g_downb);
    cudaGetSymbolAddress((void**)&pQpart, g_Qpart);
    cudaGetSymbolAddress((void**)&pScores, g_scores);
    cudaGetSymbolAddress((void**)&pADpart, g_ADpart);
    cudaGetSymbolAddress((void**)&pLpart, g_lpart);
    cudaGetSymbolAddress((void**)&pGate, g_gate);

    const int SM128 = 2 * (128 + 128) * 72 * 2;   // 73728
    cudaFuncSetAttribute(mma_mega, cudaFuncAttributeMaxDynamicSharedMemorySize, SM128);
    cudaFuncSetAttribute(mma_pipe<128, 0>, cudaFuncAttributeMaxDynamicSharedMemorySize, SM128);
    cudaFuncSetAttribute(mma_pipe<128, 1>, cudaFuncAttributeMaxDynamicSharedMemorySize, SM128);

    // L0: weight cvt + Wq pad + rk
    k_cvt_rk<<<5504, 256>>>(Wu1, Wq, aux_vals, Wvd, Wvu, aux_keys, Wr);
    // L1: H->bf16 + variance + Mslot
    k_prep_mslot<<<T + 256, 256>>>(hs, Wr, T);
    // L2: mega GEMM (Y EPI2 | Q split4 padded | AD split8)
    mma_mega<<<512, 256, SM128>>>(pHb, pWu1b, pLpart, pWqpadb, pQpart,
                                  pAvalb, pWvdb, pADpart, bu1, Wu2, T);
    // L3: reduceQ + reduceAD + gate (inline mean)
    k_post<<<512 + (T + 255) / 256, 256>>>(bu2, gw1, gb, T);
    // L4: scores = Q @ Mslot^T  [T x 1024], K=64
    mma_pipe<128, 0><<<dim3(NSLOT / 128, T / 128), 256, SM128>>>(
        pQb, pMslotb, pScores, T, NSLOT, BOT, nullptr, nullptr);
    // L5: top-8 + attention + gather
    k_topk<<<T / 8, 256>>>(aux_keys, log_rel);
    // L6: out = hs + gate * (down @ Wvu^T)
    mma_pipe<128, 1><<<dim3(HID / 128, T / 128), 256, SM128>>>(
        pDownb, pWvub, out, T, HID, VB, hs, pGate);
}

// round 9
// speedup vs baseline: 1.4607x; 1.0291x over previous
#include <cuda_runtime.h>
#include <cuda_bf16.h>
#include <cuda_fp8.h>
#include <math.h>
#include <stdint.h>

#define HID   4096
#define BOT   64
#define RDIM  48
#define NSLOT 1024
#define TOPK  8
#define VB    256
#define HU    1024
#define TMAX  4096

typedef __nv_bfloat16 bf16;

// ---------------- static scratch ----------------
__device__ bf16    g_Hb[(size_t)TMAX * HID];      // 32 MB (bf16 H for Q path)
__device__ uint8_t g_H8[(size_t)TMAX * HID];      // 16 MB (fp8 H for Y path)
__device__ uint8_t g_Wu18[HU * HID];              // 4 MB  (x64)
__device__ bf16    g_Wqpadb[128 * HID];           // 1 MB  (rows 64..127 zero)
__device__ uint8_t g_Aval8[NSLOT * HID];          // 4 MB  (x32)
__device__ uint8_t g_Wvd8[VB * HID];              // 1 MB  (x512)
__device__ uint8_t g_Wvu8[HID * VB];              // 1 MB  (x128)
__device__ uint8_t g_down8[TMAX * VB];            // 1 MB  (x512)
__device__ float   g_Qpart[4][TMAX * 128];        // 8 MB
__device__ float   g_Q[TMAX * BOT];
__device__ bf16    g_Qb[TMAX * BOT];
__device__ float   g_rk[NSLOT * RDIM];
__device__ bf16    g_Mslotb[NSLOT * BOT];
__device__ float   g_scores[(size_t)TMAX * NSLOT];
__device__ float   g_ADpart[8][NSLOT * VB];
__device__ float   g_auxdown[NSLOT * VB];
__device__ float   g_lpart[TMAX * 8];
__device__ float   g_logvar[TMAX];
__device__ float   g_gate[TMAX];

__device__ __forceinline__ float gelu_tanh(float x) {
    float x3 = x * x * x;
    return 0.5f * x * (1.0f + tanhf(0.7978845608028654f * (x + 0.044715f * x3)));
}
__device__ __forceinline__ float sigmoidf(float x) { return 1.0f / (1.0f + expf(-x)); }

// ---------------- low-level helpers ----------------
__device__ __forceinline__ uint32_t smem_u32(const void* p) {
    return (uint32_t)__cvta_generic_to_shared(p);
}
__device__ __forceinline__ void ldsm_x4(uint32_t& r0, uint32_t& r1, uint32_t& r2, uint32_t& r3,
                                        const void* p) {
    asm volatile("ldmatrix.sync.aligned.m8n8.x4.shared.b16 {%0,%1,%2,%3}, [%4];"
                 : "=r"(r0), "=r"(r1), "=r"(r2), "=r"(r3) : "r"(smem_u32(p)));
}
__device__ __forceinline__ void mma_bf16(float* c, const uint32_t* a, const uint32_t* b) {
    asm volatile(
        "mma.sync.aligned.m16n8k16.row.col.f32.bf16.bf16.f32 "
        "{%0,%1,%2,%3}, {%4,%5,%6,%7}, {%8,%9}, {%0,%1,%2,%3};"
        : "+f"(c[0]), "+f"(c[1]), "+f"(c[2]), "+f"(c[3])
        : "r"(a[0]), "r"(a[1]), "r"(a[2]), "r"(a[3]), "r"(b[0]), "r"(b[1]));
}
__device__ __forceinline__ void mma_e4m3(float* c, const uint32_t* a, const uint32_t* b) {
    asm volatile(
        "mma.sync.aligned.m16n8k32.row.col.f32.e4m3.e4m3.f32 "
        "{%0,%1,%2,%3}, {%4,%5,%6,%7}, {%8,%9}, {%0,%1,%2,%3};"
        : "+f"(c[0]), "+f"(c[1]), "+f"(c[2]), "+f"(c[3])
        : "r"(a[0]), "r"(a[1]), "r"(a[2]), "r"(a[3]), "r"(b[0]), "r"(b[1]));
}
__device__ __forceinline__ void cp16(void* s, const void* g) {
    asm volatile("cp.async.cg.shared.global [%0], [%1], 16;"
                 :: "r"(smem_u32(s)), "l"(g));
}
__device__ __forceinline__ void cp_commit() { asm volatile("cp.async.commit_group;"); }
template<int N> __device__ __forceinline__ void cp_wait() {
    asm volatile("cp.async.wait_group %0;" :: "n"(N));
}

// ---------------- shared GEMM building blocks (byte-based tiles) ----------------
// Tile = 128 rows x 128 bytes, smem row pitch 144 bytes.
__device__ __forceinline__ void load_tile(char* st, const char* G, int rowB, int r0,
                                          size_t kB, int tid) {
    #pragma unroll
    for (int i = tid; i < 1024; i += 256) {
        int r = i >> 3, off = (i & 7) * 16;
        cp16(st + r * 144 + off, G + (size_t)(r0 + r) * rowB + kB + off);
    }
}

template<bool FP8>
__device__ __forceinline__ void tile_mma(const char* Ac, const char* Bc,
                                         int wm, int wn, int lane, float acc[2][8][4]) {
    const int lrow = lane & 15, hi = (lane >> 4) * 16;
    #pragma unroll
    for (int ks = 0; ks < 4; ks++) {
        uint32_t a[2][4];
        #pragma unroll
        for (int mt = 0; mt < 2; mt++)
            ldsm_x4(a[mt][0], a[mt][1], a[mt][2], a[mt][3],
                    Ac + (wm * 32 + mt * 16 + lrow) * 144 + ks * 32 + hi);
        uint32_t bb[8][2];
        #pragma unroll
        for (int p = 0; p < 4; p++) {
            uint32_t r0, r1, r2, r3;
            ldsm_x4(r0, r1, r2, r3,
                    Bc + (wn * 64 + p * 16 + lrow) * 144 + ks * 32 + hi);
            bb[2 * p][0] = r0; bb[2 * p][1] = r2;
            bb[2 * p + 1][0] = r1; bb[2 * p + 1][1] = r3;
        }
        #pragma unroll
        for (int mt = 0; mt < 2; mt++)
            #pragma unroll
            for (int nt = 0; nt < 8; nt++) {
                if (FP8) mma_e4m3(acc[mt][nt], a[mt], bb[nt]);
                else     mma_bf16(acc[mt][nt], a[mt], bb[nt]);
            }
    }
}

// =====================================================================
// MEGA GEMM: Y(fp8, EPI2) + Q(bf16 split-K4) + AD(fp8 split-K8)
// 512 CTAs, range dispatch.
// =====================================================================
__global__ void __launch_bounds__(256, 2)
mma_mega(int T, const float* __restrict__ bu1, const float* __restrict__ wu2) {
    extern __shared__ char sm[];
    char* As = sm;                     // 2 stages x 128*144
    char* Bs = sm + 2 * 128 * 144;

    __shared__ float s_row[128][2];
    __shared__ float s_bu1[128];
    __shared__ float s_wu2[128];

    const int tid = threadIdx.x, lane = tid & 31, w = tid >> 5;
    const int wm = w & 3, wn = w >> 2;
    const int bid = blockIdx.x;

    const char *A, *B;
    float* Cout;
    int rowA, rowB, ktiles, N, m0, n0, epi, bxs = 0;
    size_t kbegB;
    float scale;
    bool fp8;

    if (bid < 256) {                   // Y: [T x 1024], K=4096 fp8
        int bx = bid & 7, by = bid >> 3;
        A = (const char*)g_H8; B = (const char*)g_Wu18;
        rowA = HID; rowB = HID; ktiles = HID / 128; kbegB = 0;
        N = 8; epi = 2; scale = 0.015625f; fp8 = true;
        m0 = by * 128; n0 = bx * 128; bxs = bx;
        Cout = g_lpart;
    } else if (bid < 384) {            // Q: [T x 128pad], bf16 split-K4
        int i = bid - 256, z = i >> 5, by = i & 31;
        A = (const char*)g_Hb; B = (const char*)g_Wqpadb;
        rowA = HID * 2; rowB = HID * 2; ktiles = 16; kbegB = (size_t)z * 2048;
        N = 128; epi = 0; scale = 1.0f; fp8 = false;
        m0 = by * 128; n0 = 0;
        Cout = g_Qpart[0] + (size_t)z * T * 128;
    } else {                           // AD: [1024 x 256], fp8 split-K8
        int i = bid - 384, z = i >> 4, r = i & 15;
        int bx = r & 1, by = r >> 1;
        A = (const char*)g_Aval8; B = (const char*)g_Wvd8;
        rowA = HID; rowB = HID; ktiles = 4; kbegB = (size_t)z * 512;
        N = VB; epi = 0; scale = 6.103515625e-05f; fp8 = true;
        m0 = by * 128; n0 = bx * 128;
        Cout = g_ADpart[0] + (size_t)z * NSLOT * VB;
    }

    if (epi == 2) {
        if (tid < 128) { s_bu1[tid] = bu1[n0 + tid]; s_wu2[tid] = wu2[n0 + tid]; }
    }

    float acc[2][8][4];
    #pragma unroll
    for (int i = 0; i < 2; i++)
        #pragma unroll
        for (int j = 0; j < 8; j++)
            #pragma unroll
            for (int q = 0; q < 4; q++) acc[i][j][q] = 0.0f;

    load_tile(As, A, rowA, m0, kbegB, tid);
    load_tile(Bs, B, rowB, n0, kbegB, tid);
    cp_commit();

    for (int kt = 0; kt < ktiles; kt++) {
        if (kt + 1 < ktiles) {
            const int st = (kt + 1) & 1;
            load_tile(As + st * 128 * 144, A, rowA, m0, kbegB + (size_t)(kt + 1) * 128, tid);
            load_tile(Bs + st * 128 * 144, B, rowB, n0, kbegB + (size_t)(kt + 1) * 128, tid);
            cp_commit();
            cp_wait<1>();
        } else {
            cp_wait<0>();
        }
        __syncthreads();
        const char* Ac = As + (kt & 1) * 128 * 144;
        const char* Bc = Bs + (kt & 1) * 128 * 144;
        if (fp8) tile_mma<true>(Ac, Bc, wm, wn, lane, acc);
        else     tile_mma<false>(Ac, Bc, wm, wn, lane, acc);
        __syncthreads();
    }

    if (epi == 2) {
        float rs[2][2];
        rs[0][0] = rs[0][1] = rs[1][0] = rs[1][1] = 0.0f;
        #pragma unroll
        for (int mt = 0; mt < 2; mt++) {
            #pragma unroll
            for (int nt = 0; nt < 8; nt++) {
                int lc = wn * 64 + nt * 8 + (lane & 3) * 2;
                float b0 = s_bu1[lc], b1 = s_bu1[lc + 1];
                float w0 = s_wu2[lc], w1 = s_wu2[lc + 1];
                rs[mt][0] += gelu_tanh(acc[mt][nt][0] * scale + b0) * w0
                           + gelu_tanh(acc[mt][nt][1] * scale + b1) * w1;
                rs[mt][1] += gelu_tanh(acc[mt][nt][2] * scale + b0) * w0
                           + gelu_tanh(acc[mt][nt][3] * scale + b1) * w1;
            }
        }
        #pragma unroll
        for (int mt = 0; mt < 2; mt++)
            #pragma unroll
            for (int h = 0; h < 2; h++) {
                rs[mt][h] += __shfl_xor_sync(0xffffffffu, rs[mt][h], 1);
                rs[mt][h] += __shfl_xor_sync(0xffffffffu, rs[mt][h], 2);
            }
        if ((lane & 3) == 0) {
            #pragma unroll
            for (int mt = 0; mt < 2; mt++)
                #pragma unroll
                for (int h = 0; h < 2; h++)
                    s_row[wm * 32 + mt * 16 + (lane >> 2) + h * 8][wn] = rs[mt][h];
        }
        __syncthreads();
        if (tid < 128)
            Cout[(size_t)(m0 + tid) * 8 + bxs] = s_row[tid][0] + s_row[tid][1];
        return;
    }

    #pragma unroll
    for (int mt = 0; mt < 2; mt++) {
        int r0 = m0 + wm * 32 + mt * 16 + (lane >> 2);
        #pragma unroll
        for (int nt = 0; nt < 8; nt++) {
            int cc = n0 + wn * 64 + nt * 8 + (lane & 3) * 2;
            size_t o0 = (size_t)r0 * N + cc;
            size_t o1 = (size_t)(r0 + 8) * N + cc;
            Cout[o0]     = acc[mt][nt][0] * scale;
            Cout[o0 + 1] = acc[mt][nt][1] * scale;
            Cout[o1]     = acc[mt][nt][2] * scale;
            Cout[o1 + 1] = acc[mt][nt][3] * scale;
        }
    }
}

// ---------------- standalone GEMM for scores (bf16) / out (fp8) ----------------
// EPI 0: C = acc*scale.  EPI 1: C = aux0(hs) + aux1(gate)[row]*acc*scale.
template<int EPI, bool FP8>
__global__ void __launch_bounds__(256, 2)
mma_pipe(const char* __restrict__ A, const char* __restrict__ B,
         float* __restrict__ C, int N, int rowA, int rowB, int ktiles, float scale,
         const float* __restrict__ aux0, const float* __restrict__ aux1) {
    extern __shared__ char sm[];
    char* As = sm;
    char* Bs = sm + 2 * 128 * 144;

    const int tid = threadIdx.x, lane = tid & 31, w = tid >> 5;
    const int wm = w & 3, wn = w >> 2;
    const int m0 = blockIdx.y * 128, n0 = blockIdx.x * 128;

    float acc[2][8][4];
    #pragma unroll
    for (int i = 0; i < 2; i++)
        #pragma unroll
        for (int j = 0; j < 8; j++)
            #pragma unroll
            for (int q = 0; q < 4; q++) acc[i][j][q] = 0.0f;

    load_tile(As, A, rowA, m0, 0, tid);
    load_tile(Bs, B, rowB, n0, 0, tid);
    cp_commit();

    for (int kt = 0; kt < ktiles; kt++) {
        if (kt + 1 < ktiles) {
            const int st = (kt + 1) & 1;
            load_tile(As + st * 128 * 144, A, rowA, m0, (size_t)(kt + 1) * 128, tid);
            load_tile(Bs + st * 128 * 144, B, rowB, n0, (size_t)(kt + 1) * 128, tid);
            cp_commit();
            cp_wait<1>();
        } else {
            cp_wait<0>();
        }
        __syncthreads();
        const char* Ac = As + (kt & 1) * 128 * 144;
        const char* Bc = Bs + (kt & 1) * 128 * 144;
        tile_mma<FP8>(Ac, Bc, wm, wn, lane, acc);
        __syncthreads();
    }

    #pragma unroll
    for (int mt = 0; mt < 2; mt++) {
        int r0 = m0 + wm * 32 + mt * 16 + (lane >> 2);
        float g0 = 0.0f, g1 = 0.0f;
        if (EPI == 1) { g0 = aux1[r0] * scale; g1 = aux1[r0 + 8] * scale; }
        #pragma unroll
        for (int nt = 0; nt < 8; nt++) {
            int cc = n0 + wn * 64 + nt * 8 + (lane & 3) * 2;
            size_t o0 = (size_t)r0 * N + cc;
            size_t o1 = (size_t)(r0 + 8) * N + cc;
            if (EPI == 0) {
                C[o0]     = acc[mt][nt][0] * scale;
                C[o0 + 1] = acc[mt][nt][1] * scale;
                C[o1]     = acc[mt][nt][2] * scale;
                C[o1 + 1] = acc[mt][nt][3] * scale;
            } else {
                C[o0]     = aux0[o0]     + g0 * acc[mt][nt][0];
                C[o0 + 1] = aux0[o0 + 1] + g0 * acc[mt][nt][1];
                C[o1]     = aux0[o1]     + g1 * acc[mt][nt][2];
                C[o1 + 1] = aux0[o1 + 1] + g1 * acc[mt][nt][3];
            }
        }
    }
}

// =====================================================================
// L0: weight conversions (bf16 + scaled fp8) + Wq pad-zero + rk dots
// =====================================================================
__device__ __forceinline__ void cvt1(const float* in, bf16* out, size_t i) {
    float4 f = ((const float4*)in)[i];
    ((__nv_bfloat162*)out)[2 * i]     = __floats2bfloat162_rn(f.x, f.y);
    ((__nv_bfloat162*)out)[2 * i + 1] = __floats2bfloat162_rn(f.z, f.w);
}
__device__ __forceinline__ uint32_t cvt_fp8x4(float4 f, float s) {
    __nv_fp8x2_storage_t lo = __nv_cvt_float2_to_fp8x2(make_float2(f.x * s, f.y * s),
                                                       __NV_SATFINITE, __NV_E4M3);
    __nv_fp8x2_storage_t hi = __nv_cvt_float2_to_fp8x2(make_float2(f.z * s, f.w * s),
                                                       __NV_SATFINITE, __NV_E4M3);
    return (uint32_t)lo | ((uint32_t)hi << 16);
}
__device__ __forceinline__ void cvt8(const float* in, uint8_t* out, size_t i, float s) {
    ((uint32_t*)out)[i] = cvt_fp8x4(((const float4*)in)[i], s);
}
// cvt blocks 5248 | pad 64 | rk 192 -> grid 5504
__global__ void k_cvt_rk(const float* w1, const float* w2, const float* w3,
                         const float* w4, const float* w5,
                         const float* aux_keys, const float* Wr) {
    const int bid = blockIdx.x, tid = threadIdx.x;
    if (bid < 5248) {
        size_t base = (size_t)(bid * 256 + tid) * 2;
        #pragma unroll
        for (int j = 0; j < 2; j++) {
            size_t i = base + j;
            if (i < 1048576)            cvt8(w1, g_Wu18, i, 64.0f);
            else if (i < 1114112)       cvt1(w2, g_Wqpadb, i - 1048576);
            else if (i < 2162688)       cvt8(w3, g_Aval8, i - 1114112, 32.0f);
            else if (i < 2424832)       cvt8(w4, g_Wvd8, i - 2162688, 512.0f);
            else if (i < 2686976)       cvt8(w5, g_Wvu8, i - 2424832, 128.0f);
        }
    } else if (bid < 5312) {
        int u = (bid - 5248) * 256 + tid;
        uint4 z = make_uint4(0, 0, 0, 0);
        ((uint4*)g_Wqpadb)[32768 + 2 * u]     = z;
        ((uint4*)g_Wqpadb)[32768 + 2 * u + 1] = z;
    } else {
        int g = (bid - 5312) * 256 + tid;      // [0, 49152)
        int n = g / RDIM, r = g % RDIM;
        const float4* ar = (const float4*)(aux_keys + (size_t)n * BOT);
        const float4* wr = (const float4*)(Wr + (size_t)r * BOT);
        float s = 0.0f;
        #pragma unroll
        for (int i = 0; i < 16; i++) {
            float4 a = ar[i], b = wr[i];
            s += a.x * b.x + a.y * b.y + a.z * b.z + a.w * b.w;
        }
        g_rk[n * RDIM + r] = s;
    }
}

// =====================================================================
// L1: hs -> bf16 + fp8 + log1p(var) (+ mslot blocks)
// =====================================================================
__global__ void k_prep_mslot(const float* __restrict__ hs, const float* __restrict__ Wr,
                             int T) {
    if ((int)blockIdx.x < T) {
        __shared__ float sh1[256], sh2[256];
        const int t = blockIdx.x, tid = threadIdx.x;
        const float4* row = (const float4*)(hs + (size_t)t * HID);
        __nv_bfloat162* orow = (__nv_bfloat162*)(g_Hb + (size_t)t * HID);
        uint32_t* o8 = (uint32_t*)(g_H8 + (size_t)t * HID);
        float s = 0.0f, s2 = 0.0f;
        float4 f[4];
        #pragma unroll
        for (int i = 0; i < 4; i++) f[i] = row[tid + i * 256];
        #pragma unroll
        for (int i = 0; i < 4; i++) {
            int c = tid + i * 256;
            s += f[i].x + f[i].y + f[i].z + f[i].w;
            s2 += f[i].x * f[i].x + f[i].y * f[i].y + f[i].z * f[i].z + f[i].w * f[i].w;
            orow[2 * c]     = __floats2bfloat162_rn(f[i].x, f[i].y);
            orow[2 * c + 1] = __floats2bfloat162_rn(f[i].z, f[i].w);
            o8[c] = cvt_fp8x4(f[i], 1.0f);
        }
        sh1[tid] = s; sh2[tid] = s2;
        __syncthreads();
        for (int off = 128; off > 0; off >>= 1) {
            if (tid < off) { sh1[tid] += sh1[tid + off]; sh2[tid] += sh2[tid + off]; }
            __syncthreads();
        }
        if (tid == 0) {
            float mean = sh1[0] * (1.0f / HID);
            float var  = sh2[0] * (1.0f / HID) - mean * mean;
            g_logvar[t] = log1pf(var);
        }
    } else {
        int idx = (blockIdx.x - T) * 256 + threadIdx.x;
        int n = idx >> 6, c = idx & 63;
        float s = 0.0f;
        #pragma unroll
        for (int r = 0; r < RDIM; r++) s += g_rk[n * RDIM + r] * Wr[r * BOT + c];
        g_Mslotb[idx] = __float2bfloat16(s);
    }
}

// =====================================================================
// L3: reduceQ (256) + reduceAD (256) + gate (inline mean)
// =====================================================================
__global__ void k_post(const float* __restrict__ bu2, const float* __restrict__ gw1,
                       const float* __restrict__ gb, int T) {
    const int bid = blockIdx.x, tid = threadIdx.x;
    if (bid < 256) {
        int i = bid * 256 + tid;               // [0, 65536)
        int t = i >> 4, c4 = i & 15;
        size_t off = (size_t)t * 128 + c4 * 4;
        float4 r = *(const float4*)(&g_Qpart[0][off]);
        #pragma unroll
        for (int z = 1; z < 4; z++) {
            float4 p = *(const float4*)(&g_Qpart[z][off]);
            r.x += p.x; r.y += p.y; r.z += p.z; r.w += p.w;
        }
        ((float4*)g_Q)[i] = r;
        ((__nv_bfloat162*)g_Qb)[2 * i]     = __floats2bfloat162_rn(r.x, r.y);
        ((__nv_bfloat162*)g_Qb)[2 * i + 1] = __floats2bfloat162_rn(r.z, r.w);
    } else if (bid < 512) {
        int i = (bid - 256) * 256 + tid;
        float4 r = ((const float4*)g_ADpart[0])[i];
        #pragma unroll
        for (int z = 1; z < 8; z++) {
            float4 p = ((const float4*)g_ADpart[z])[i];
            r.x += p.x; r.y += p.y; r.z += p.z; r.w += p.w;
        }
        ((float4*)g_auxdown)[i] = r;
    } else {
        __shared__ float sh[256];
        __shared__ float s_mean;
        float s = 0.0f;
        for (int i = tid; i < T; i += 256) s += g_logvar[i];
        sh[tid] = s;
        __syncthreads();
        for (int off = 128; off > 0; off >>= 1) {
            if (tid < off) sh[tid] += sh[tid + off];
            __syncthreads();
        }
        if (tid == 0) s_mean = sh[0] / (float)T;
        __syncthreads();
        int t = (bid - 512) * 256 + tid;
        if (t < T) {
            float acc = 0.0f;
            #pragma unroll
            for (int i = 0; i < 8; i++) acc += g_lpart[t * 8 + i];
            float learned = acc + bu2[0];
            float nv = g_logvar[t] / (s_mean + 1e-6f);
            float u = fminf(fmaxf(nv * 0.5f + sigmoidf(learned) * 2.5f, 0.0f), 5.0f);
            float un = fminf(fmaxf((u - 0.5f) * (1.0f / 1.5f), 0.0f), 1.0f);
            float g = sigmoidf(gw1[0] * un + gb[0]);
            g_gate[t] = (g < 0.05f) ? 0.0f : g;
        }
    }
}

// ---------------- top-k + attention + bottleneck gather (-> fp8 down) ----------------
__global__ void k_topk(const float* __restrict__ aux_keys,
                       const float* __restrict__ log_rel) {
    __shared__ float s_w[8][TOPK];
    __shared__ int   s_idx[8][TOPK];
    const int tid = threadIdx.x, w = tid >> 5, lane = tid & 31;
    const int t = blockIdx.x * 8 + w;
    const float inv_sqrt_r = 0.14433756729740643f;

    float v[32];
    const float* srow = g_scores + (size_t)t * NSLOT;
    #pragma unroll
    for (int i = 0; i < 32; i++)
        v[i] = srow[i * 32 + lane] * inv_sqrt_r + __ldg(&log_rel[i * 32 + lane]);

    for (int sel = 0; sel < TOPK; sel++) {
        float m = -INFINITY; int mi = NSLOT;
        #pragma unroll
        for (int i = 0; i < 32; i++)
            if (v[i] > m) { m = v[i]; mi = i * 32 + lane; }
        #pragma unroll
        for (int off = 16; off >= 1; off >>= 1) {
            float om = __shfl_xor_sync(0xffffffffu, m, off);
            int   omi = __shfl_xor_sync(0xffffffffu, mi, off);
            if (om > m || (om == m && omi < mi)) { m = om; mi = omi; }
        }
        if ((mi & 31) == lane) v[mi >> 5] = -INFINITY;
        if (lane == 0) s_idx[w][sel] = mi;
    }
    __syncwarp();

    if (lane < TOPK) {
        int idx = s_idx[w][lane];
        const float* qr = &g_Q[(size_t)t * BOT];
        const float* kr = &aux_keys[(size_t)idx * BOT];
        float dot = 0.0f;
        #pragma unroll
        for (int c = 0; c < BOT; c++) dot += qr[c] * kr[c];
        float a = dot * 0.125f + log_rel[idx];
        float mx = a;
        #pragma unroll
        for (int off = 4; off >= 1; off >>= 1)
            mx = fmaxf(mx, __shfl_xor_sync(0xffu, mx, off, 8));
        float e = expf(a - mx);
        float se = e;
        #pragma unroll
        for (int off = 4; off >= 1; off >>= 1)
            se += __shfl_xor_sync(0xffu, se, off, 8);
        s_w[w][lane] = e / se;
    }
    __syncwarp();

    int   idxs[TOPK]; float ws[TOPK];
    #pragma unroll
    for (int k = 0; k < TOPK; k++) { idxs[k] = s_idx[w][k]; ws[k] = s_w[w][k]; }
    #pragma unroll
    for (int j = 0; j < VB / 32; j++) {
        int col = lane + j * 32;
        float acc = 0.0f;
        #pragma unroll
        for (int k = 0; k < TOPK; k++)
            acc += ws[k] * g_auxdown[(size_t)idxs[k] * VB + col];
        g_down8[(size_t)t * VB + col] =
            (uint8_t)__nv_cvt_float_to_fp8(acc * 512.0f, __NV_SATFINITE, __NV_E4M3);
    }
}

// ---------------- launch ----------------
extern "C" void kernel_launch(void* const* d_in, const int* in_sizes, int n_in,
                              void* d_out, int out_size) {
    const float* hs       = (const float*)d_in[0];
    const float* Wq       = (const float*)d_in[1];
    const float* Wr       = (const float*)d_in[2];
    const float* aux_keys = (const float*)d_in[3];
    const float* aux_vals = (const float*)d_in[4];
    const float* Wvd      = (const float*)d_in[5];
    const float* Wvu      = (const float*)d_in[6];
    const float* Wu1      = (const float*)d_in[7];
    const float* bu1      = (const float*)d_in[8];
    const float* Wu2      = (const float*)d_in[9];
    const float* bu2      = (const float*)d_in[10];
    const float* gw1      = (const float*)d_in[11];
    const float* gb       = (const float*)d_in[12];
    const float* log_rel  = (const float*)d_in[13];
    float* out = (float*)d_out;

    const int T = in_sizes[0] / HID;   // 4096

    char *pQb, *pMslotb, *pDown8, *pWvu8;
    float *pScores, *pGate;
    cudaGetSymbolAddress((void**)&pQb, g_Qb);
    cudaGetSymbolAddress((void**)&pMslotb, g_Mslotb);
    cudaGetSymbolAddress((void**)&pDown8, g_down8);
    cudaGetSymbolAddress((void**)&pWvu8, g_Wvu8);
    cudaGetSymbolAddress((void**)&pScores, g_scores);
    cudaGetSymbolAddress((void**)&pGate, g_gate);

    const int SM = 4 * 128 * 144;      // 73728
    cudaFuncSetAttribute(mma_mega, cudaFuncAttributeMaxDynamicSharedMemorySize, SM);
    cudaFuncSetAttribute(mma_pipe<0, false>, cudaFuncAttributeMaxDynamicSharedMemorySize, SM);
    cudaFuncSetAttribute(mma_pipe<1, true>,  cudaFuncAttributeMaxDynamicSharedMemorySize, SM);

    // L0: weight cvt (fp8/bf16) + Wq pad + rk
    k_cvt_rk<<<5504, 256>>>(Wu1, Wq, aux_vals, Wvd, Wvu, aux_keys, Wr);
    // L1: H->bf16+fp8 + variance + Mslot
    k_prep_mslot<<<T + 256, 256>>>(hs, Wr, T);
    // L2: mega GEMM (Y fp8 EPI2 | Q bf16 split4 | AD fp8 split8)
    mma_mega<<<512, 256, SM>>>(T, bu1, Wu2);
    // L3: reduceQ + reduceAD + gate
    k_post<<<512 + (T + 255) / 256, 256>>>(bu2, gw1, gb, T);
    // L4: scores = Q @ Mslot^T  [T x 1024], K=64 bf16 (1 tile)
    mma_pipe<0, false><<<dim3(NSLOT / 128, T / 128), 256, SM>>>(
        pQb, pMslotb, pScores, NSLOT, 128, 128, 1, 1.0f, nullptr, nullptr);
    // L5: top-8 + attention + gather -> fp8 down
    k_topk<<<T / 8, 256>>>(aux_keys, log_rel);
    // L6: out = hs + gate * (down @ Wvu^T) / 65536   fp8, K=256 (2 tiles)
    mma_pipe<1, true><<<dim3(HID / 128, T / 128), 256, SM>>>(
        pDown8, pWvu8, out, HID, 256, 256, 2, 1.52587890625e-05f, hs, pGate);
}